// round 4
// baseline (speedup 1.0000x reference)
#include <cuda_runtime.h>
#include <cstdint>

// ---------------------------------------------------------------------------
// Problem constants
// ---------------------------------------------------------------------------
#define BB 8
#define TT 1024
#define CC 1024
#define HH 16
#define DD 64
#define NTOK (BB * TT)           // 8192
#define SCALE_ATTN 0.07216878364870323f  // 1/sqrt(3*C/H) = 1/sqrt(192)

// ---------------------------------------------------------------------------
// Scratch (device globals; no dynamic allocation allowed)
// ---------------------------------------------------------------------------
__device__ float g_h[NTOK * CC];          // ln1 out (tf32 bits)
__device__ float g_qkv[NTOK * 3 * CC];    // qkv
__device__ float g_y[NTOK * CC];          // attn out (tf32 bits)
__device__ float g_h2[NTOK * CC];         // ln2 out (tf32 bits)
__device__ float g_mid[NTOK * 4 * CC];    // mlp hidden (tf32 bits)
// packed tf32 weights: Wqkv(3M) Wproj(1M) W1(4M) W2(4M)
#define OFF_QKV  0
#define OFF_PROJ (CC * 3 * CC)
#define OFF_W1   (OFF_PROJ + CC * CC)
#define OFF_W2   (OFF_W1 + CC * 4 * CC)
#define WP_TOTAL (OFF_W2 + 4 * CC * CC)
__device__ float g_wp[WP_TOTAL];

// ---------------------------------------------------------------------------
// Helpers
// ---------------------------------------------------------------------------
__device__ __forceinline__ uint32_t f2tf32(float f) {
    uint32_t u;
    asm("cvt.rna.tf32.f32 %0, %1;" : "=r"(u) : "f"(f));
    return u;
}
__device__ __forceinline__ float tf32r(float f) { return __uint_as_float(f2tf32(f)); }

__device__ __forceinline__ void mma_tf32(float* c, const uint32_t* a, const uint32_t* b) {
    asm volatile(
        "mma.sync.aligned.m16n8k8.row.col.f32.tf32.tf32.f32 "
        "{%0,%1,%2,%3}, {%4,%5,%6,%7}, {%8,%9}, {%0,%1,%2,%3};"
        : "+f"(c[0]), "+f"(c[1]), "+f"(c[2]), "+f"(c[3])
        : "r"(a[0]), "r"(a[1]), "r"(a[2]), "r"(a[3]), "r"(b[0]), "r"(b[1]));
}

__device__ __forceinline__ void cp_async16(void* smem_ptr, const void* gptr) {
    uint32_t sp = (uint32_t)__cvta_generic_to_shared(smem_ptr);
    asm volatile("cp.async.ca.shared.global [%0], [%1], 16;" :: "r"(sp), "l"(gptr));
}

// ---------------------------------------------------------------------------
// Weight pack kernel: W[K][N] row-major -> tf32-rounded fragment-order blocks.
// One 256-thread block handles a (16k x 128n) tile = 2048 floats.
// Packed layout: blk = (it*nt + n_idx)*4 + ks*2 + w  (512 floats each)
//   within blk: lane l holds 16 floats; quad j2 stored at slot (j2+(l>>1))&3,
//   quad content: [B(tig,2j2), B(tig+4,2j2), B(tig,2j2+1), B(tig+4,2j2+1)]
//   where row k = it*16+ks*8+tig(+4), col n = n_idx*128+w*64+gid+8j.
// ---------------------------------------------------------------------------
__global__ __launch_bounds__(256)
void pack_w_kernel(const float* __restrict__ W, float* __restrict__ P, int K, int N) {
    __shared__ float tile[16][132];
    const int nt = N >> 7;
    const int it = blockIdx.x / nt;
    const int n_idx = blockIdx.x % nt;
    const int tid = threadIdx.x;

    // coalesced read 16x128
    #pragma unroll
    for (int s = 0; s < 2; s++) {
        const int seg = tid * 2 + s;          // 0..511 float4
        const int r = seg >> 5;               // 0..15
        const int cc = (seg & 31) << 2;       // 0..124
        float4 v = *(const float4*)(W + (size_t)(it * 16 + r) * N + n_idx * 128 + cc);
        tile[r][cc + 0] = v.x; tile[r][cc + 1] = v.y;
        tile[r][cc + 2] = v.z; tile[r][cc + 3] = v.w;
    }
    __syncthreads();

    // coalesced packed write: 8 floats per thread
    float* dst = P + ((size_t)it * nt + n_idx) * 2048;
    #pragma unroll
    for (int o = 0; o < 8; o++) {
        const int flat = tid * 8 + o;         // 0..2047
        const int blkL = flat >> 9;           // 0..3
        const int w    = blkL & 1;
        const int ks   = blkL >> 1;
        const int rem  = flat & 511;
        const int l    = rem >> 4;            // lane 0..31
        const int slot = (rem >> 2) & 3;
        const int e    = rem & 3;
        const int gid  = l >> 2, tig = l & 3;
        const int j2   = (slot - (l >> 1)) & 3;
        const int j    = 2 * j2 + (e >> 1);
        const int kr   = ks * 8 + tig + (e & 1) * 4;
        const int col  = w * 64 + gid + j * 8;
        dst[flat] = tf32r(tile[kr][col]);
    }
}

// ---------------------------------------------------------------------------
// LayerNorm: one block per row; output rounded to tf32 (feeds GEMM A).
// ---------------------------------------------------------------------------
__global__ __launch_bounds__(256)
void ln_kernel(const float* __restrict__ x, const float* __restrict__ g,
               const float* __restrict__ b, float* __restrict__ out) {
    __shared__ float rs[8];
    __shared__ float rq[8];
    const int row = blockIdx.x;
    const float* xr = x + (size_t)row * CC;
    float* yr = out + (size_t)row * CC;
    const int c = threadIdx.x * 4;

    float4 v = *(const float4*)(xr + c);
    float s  = v.x + v.y + v.z + v.w;
    float sq = v.x * v.x + v.y * v.y + v.z * v.z + v.w * v.w;
    #pragma unroll
    for (int o = 16; o; o >>= 1) {
        s  += __shfl_xor_sync(0xffffffffu, s, o);
        sq += __shfl_xor_sync(0xffffffffu, sq, o);
    }
    if ((threadIdx.x & 31) == 0) {
        rs[threadIdx.x >> 5] = s;
        rq[threadIdx.x >> 5] = sq;
    }
    __syncthreads();
    s = 0.f; sq = 0.f;
    #pragma unroll
    for (int i = 0; i < 8; i++) { s += rs[i]; sq += rq[i]; }

    const float mean = s * (1.f / CC);
    const float var  = sq * (1.f / CC) - mean * mean;
    const float rstd = rsqrtf(var + 1e-5f);

    float4 g4 = *(const float4*)(g + c);
    float4 b4 = *(const float4*)(b + c);
    float4 o;
    o.x = tf32r((v.x - mean) * rstd * g4.x + b4.x);
    o.y = tf32r((v.y - mean) * rstd * g4.y + b4.y);
    o.z = tf32r((v.z - mean) * rstd * g4.z + b4.z);
    o.w = tf32r((v.w - mean) * rstd * g4.w + b4.w);
    *(float4*)(yr + c) = o;
}

// ---------------------------------------------------------------------------
// TF32 tensor GEMM: C = A[M,K] @ Bpacked[K,N] + bias (+Res | relu)
// 128x128 CTA tile, BK=16, 4-stage cp.async, 8 warps (4x2), warp tile 32x64.
// A in smem row-major stride 20 (conflict-free scalar LDS).
// B in smem fragment-packed (conflict-free LDS.128 via quad swizzle).
// EPI: 0 = bias, 1 = bias + residual, 2 = bias + relu (tf32-rounded out)
// ---------------------------------------------------------------------------
#define STAGES 4
#define A_STG 2560   // 128*20 floats
#define B_STG 2048   // 4 blocks * 512 floats
#define GEMM_SMEM ((STAGES * (A_STG + B_STG)) * 4)   // 73728 B

template <int EPI>
__global__ __launch_bounds__(256, 2)
void tgemm_kernel(const float* __restrict__ A, const float* __restrict__ Bp,
                  const float* __restrict__ bias, const float* __restrict__ Res,
                  float* __restrict__ C, int M, int N, int K) {
    extern __shared__ float smem[];
    float* sA = smem;                       // STAGES * A_STG
    float* sB = smem + STAGES * A_STG;      // STAGES * B_STG

    const int tid  = threadIdx.x;
    const int warp = tid >> 5;
    const int lane = tid & 31;
    const int gid  = lane >> 2;
    const int tig  = lane & 3;
    const int wcol = warp & 1;              // n half (0/1 -> +0/+64)
    const int wm   = (warp >> 1) * 32;      // m offset
    const int m0   = blockIdx.y * 128;
    const int n0   = blockIdx.x * 128;
    const int nt   = N >> 7;
    const int NIT  = K >> 4;

    float acc[2][8][4];
    #pragma unroll
    for (int i = 0; i < 2; i++)
        #pragma unroll
        for (int j = 0; j < 8; j++)
            #pragma unroll
            for (int r = 0; r < 4; r++) acc[i][j][r] = 0.f;

    auto load_tile = [&](int it, int stage) {
        float* dA = sA + stage * A_STG;
        float* dB = sB + stage * B_STG;
        const int kbase = it * 16;
        #pragma unroll
        for (int s = 0; s < 2; s++) {
            const int seg = tid * 2 + s;          // 0..511
            const int r  = seg >> 2;
            const int kk = (seg & 3) << 2;
            cp_async16(dA + r * 20 + kk, A + (size_t)(m0 + r) * K + kbase + kk);
        }
        const float* src = Bp + ((size_t)it * nt + (n0 >> 7)) * 2048;
        #pragma unroll
        for (int s = 0; s < 2; s++) {
            const int seg = tid * 2 + s;          // 0..511 float4
            cp_async16(dB + seg * 4, src + seg * 4);
        }
        asm volatile("cp.async.commit_group;");
    };

    load_tile(0, 0);
    load_tile(1, 1);
    load_tile(2, 2);

    for (int it = 0; it < NIT; it++) {
        const int stage = it & (STAGES - 1);
        asm volatile("cp.async.wait_group %0;" :: "n"(STAGES - 2));
        __syncthreads();

        if (it + STAGES - 1 < NIT) load_tile(it + STAGES - 1, (it + STAGES - 1) & (STAGES - 1));

        const uint32_t* uA = (const uint32_t*)(sA + stage * A_STG);
        const uint32_t* uB = (const uint32_t*)(sB + stage * B_STG);

        #pragma unroll
        for (int ks = 0; ks < 2; ks++) {
            uint32_t af[2][4];
            #pragma unroll
            for (int i = 0; i < 2; i++) {
                const int rb = wm + i * 16 + gid;
                const int base = rb * 20 + ks * 8 + tig;
                af[i][0] = uA[base];
                af[i][1] = uA[base + 8 * 20];
                af[i][2] = uA[base + 4];
                af[i][3] = uA[base + 8 * 20 + 4];
            }
            uint32_t bf[8][2];
            const uint32_t* blk = uB + (ks * 2 + wcol) * 512 + lane * 16;
            #pragma unroll
            for (int q = 0; q < 4; q++) {
                const int slot = ((q + (lane >> 1)) & 3) << 2;
                uint4 b4 = *(const uint4*)(blk + slot);
                bf[2 * q][0]     = b4.x;
                bf[2 * q][1]     = b4.y;
                bf[2 * q + 1][0] = b4.z;
                bf[2 * q + 1][1] = b4.w;
            }
            #pragma unroll
            for (int i = 0; i < 2; i++)
                #pragma unroll
                for (int j = 0; j < 8; j++)
                    mma_tf32(acc[i][j], af[i], bf[j]);
        }
        __syncthreads();
    }

    // epilogue
    #pragma unroll
    for (int i = 0; i < 2; i++) {
        #pragma unroll
        for (int half = 0; half < 2; half++) {
            const int r = m0 + wm + i * 16 + gid + half * 8;
            const size_t rowoff = (size_t)r * N;
            #pragma unroll
            for (int j = 0; j < 8; j++) {
                const int c = n0 + wcol * 64 + j * 8 + tig * 2;
                float v0 = acc[i][j][half * 2 + 0] + bias[c];
                float v1 = acc[i][j][half * 2 + 1] + bias[c + 1];
                if (EPI == 1) {
                    float2 r2 = *(const float2*)(Res + rowoff + c);
                    v0 += r2.x; v1 += r2.y;
                }
                if (EPI == 2) {
                    v0 = tf32r(fmaxf(v0, 0.f));
                    v1 = tf32r(fmaxf(v1, 0.f));
                }
                float2 o; o.x = v0; o.y = v1;
                *(float2*)(C + rowoff + c) = o;
            }
        }
    }
}

// ---------------------------------------------------------------------------
// Causal flash attention, fp32 (tensor-core conversion is next round).
// Output rounded to tf32 (feeds proj GEMM A).
// ---------------------------------------------------------------------------
__global__ __launch_bounds__(256)
void attn_kernel(const float* __restrict__ qkv, float* __restrict__ y) {
    __shared__ __align__(16) float Qs[64][64];
    __shared__ __align__(16) float KPs[64][64];
    __shared__ __align__(16) float Vs[64][64];

    const int tid = threadIdx.x;
    const int qb = blockIdx.x;
    const int h  = blockIdx.y;
    const int b  = blockIdx.z;
    const int rg = tid >> 4;
    const int cg = tid & 15;

    const size_t base = (size_t)b * TT * (3 * CC) + (size_t)h * DD;

    for (int i4 = tid; i4 < 1024; i4 += 256) {
        const int r = i4 >> 4;
        const int d0 = (i4 & 15) << 2;
        float4 q4 = *(const float4*)(qkv + base + (size_t)(qb * 64 + r) * (3 * CC) + d0);
        Qs[d0 + 0][r] = q4.x * SCALE_ATTN;
        Qs[d0 + 1][r] = q4.y * SCALE_ATTN;
        Qs[d0 + 2][r] = q4.z * SCALE_ATTN;
        Qs[d0 + 3][r] = q4.w * SCALE_ATTN;
    }

    float m[4], l[4], acc[4][4];
    #pragma unroll
    for (int i = 0; i < 4; i++) {
        m[i] = -1e30f; l[i] = 0.f;
        #pragma unroll
        for (int j = 0; j < 4; j++) acc[i][j] = 0.f;
    }

    for (int kb = 0; kb <= qb; kb++) {
        __syncthreads();
        for (int i4 = tid; i4 < 1024; i4 += 256) {
            const int c = i4 >> 4;
            const int d0 = (i4 & 15) << 2;
            const size_t kaddr = base + CC + (size_t)(kb * 64 + c) * (3 * CC) + d0;
            float4 k4 = *(const float4*)(qkv + kaddr);
            KPs[d0 + 0][c] = k4.x;
            KPs[d0 + 1][c] = k4.y;
            KPs[d0 + 2][c] = k4.z;
            KPs[d0 + 3][c] = k4.w;
            float4 v4 = *(const float4*)(qkv + kaddr + CC);
            *(float4*)&Vs[c][d0] = v4;
        }
        __syncthreads();

        float s[4][4];
        #pragma unroll
        for (int i = 0; i < 4; i++)
            #pragma unroll
            for (int j = 0; j < 4; j++) s[i][j] = 0.f;

        #pragma unroll 8
        for (int d = 0; d < 64; d++) {
            float qa[4], kk[4];
            *(float4*)qa = *(const float4*)&Qs[d][rg << 2];
            *(float4*)kk = *(const float4*)&KPs[d][cg << 2];
            #pragma unroll
            for (int i = 0; i < 4; i++)
                #pragma unroll
                for (int j = 0; j < 4; j++)
                    s[i][j] = fmaf(qa[i], kk[j], s[i][j]);
        }

        if (kb == qb) {
            #pragma unroll
            for (int i = 0; i < 4; i++)
                #pragma unroll
                for (int j = 0; j < 4; j++)
                    if ((cg << 2) + j > (rg << 2) + i) s[i][j] = -1e30f;
        }

        float rmax[4], rsum[4], corr[4];
        #pragma unroll
        for (int i = 0; i < 4; i++)
            rmax[i] = fmaxf(fmaxf(s[i][0], s[i][1]), fmaxf(s[i][2], s[i][3]));
        #pragma unroll
        for (int o = 1; o < 16; o <<= 1)
            #pragma unroll
            for (int i = 0; i < 4; i++)
                rmax[i] = fmaxf(rmax[i], __shfl_xor_sync(0xffffffffu, rmax[i], o));
        #pragma unroll
        for (int i = 0; i < 4; i++) {
            const float mn = fmaxf(m[i], rmax[i]);
            corr[i] = __expf(m[i] - mn);
            m[i] = mn;
            rsum[i] = 0.f;
            #pragma unroll
            for (int j = 0; j < 4; j++) {
                s[i][j] = __expf(s[i][j] - mn);
                rsum[i] += s[i][j];
            }
        }
        #pragma unroll
        for (int o = 1; o < 16; o <<= 1)
            #pragma unroll
            for (int i = 0; i < 4; i++)
                rsum[i] += __shfl_xor_sync(0xffffffffu, rsum[i], o);
        #pragma unroll
        for (int i = 0; i < 4; i++) {
            l[i] = l[i] * corr[i] + rsum[i];
            #pragma unroll
            for (int j = 0; j < 4; j++) acc[i][j] *= corr[i];
        }

        __syncthreads();
        #pragma unroll
        for (int j = 0; j < 4; j++) {
            const int c = (cg << 2) + j;
            *(float4*)&KPs[c][rg << 2] = make_float4(s[0][j], s[1][j], s[2][j], s[3][j]);
        }
        __syncthreads();

        #pragma unroll 8
        for (int c = 0; c < 64; c++) {
            float p[4], vv[4];
            *(float4*)p  = *(const float4*)&KPs[c][rg << 2];
            *(float4*)vv = *(const float4*)&Vs[c][cg << 2];
            #pragma unroll
            for (int i = 0; i < 4; i++)
                #pragma unroll
                for (int j = 0; j < 4; j++)
                    acc[i][j] = fmaf(p[i], vv[j], acc[i][j]);
        }
    }

    #pragma unroll
    for (int i = 0; i < 4; i++) {
        const float inv = 1.f / l[i];
        const int r = (rg << 2) + i;
        const size_t off = ((size_t)(b * TT + qb * 64 + r)) * CC + h * DD + (cg << 2);
        float4 o = make_float4(tf32r(acc[i][0] * inv), tf32r(acc[i][1] * inv),
                               tf32r(acc[i][2] * inv), tf32r(acc[i][3] * inv));
        *(float4*)(y + off) = o;
    }
}

// ---------------------------------------------------------------------------
// Launch
// ---------------------------------------------------------------------------
extern "C" void kernel_launch(void* const* d_in, const int* in_sizes, int n_in,
                              void* d_out, int out_size) {
    const float* x     = (const float*)d_in[0];
    const float* Wqkv  = (const float*)d_in[1];
    const float* bqkv  = (const float*)d_in[2];
    const float* Wproj = (const float*)d_in[3];
    const float* bproj = (const float*)d_in[4];
    const float* ln1_g = (const float*)d_in[5];
    const float* ln1_b = (const float*)d_in[6];
    const float* ln2_g = (const float*)d_in[7];
    const float* ln2_b = (const float*)d_in[8];
    const float* W1    = (const float*)d_in[9];
    const float* b1    = (const float*)d_in[10];
    const float* W2    = (const float*)d_in[11];
    const float* b2    = (const float*)d_in[12];
    float* out = (float*)d_out;

    float *h, *qkv, *y, *h2, *mid, *wp;
    cudaGetSymbolAddress((void**)&h,   g_h);
    cudaGetSymbolAddress((void**)&qkv, g_qkv);
    cudaGetSymbolAddress((void**)&y,   g_y);
    cudaGetSymbolAddress((void**)&h2,  g_h2);
    cudaGetSymbolAddress((void**)&mid, g_mid);
    cudaGetSymbolAddress((void**)&wp,  g_wp);

    static int smem_set = 0;
    if (!smem_set) {
        cudaFuncSetAttribute(tgemm_kernel<0>, cudaFuncAttributeMaxDynamicSharedMemorySize, GEMM_SMEM);
        cudaFuncSetAttribute(tgemm_kernel<1>, cudaFuncAttributeMaxDynamicSharedMemorySize, GEMM_SMEM);
        cudaFuncSetAttribute(tgemm_kernel<2>, cudaFuncAttributeMaxDynamicSharedMemorySize, GEMM_SMEM);
        smem_set = 1;
    }

    // 0. pack + round weights (runs inside graph; deterministic)
    pack_w_kernel<<<(CC / 16) * (3 * CC / 128), 256>>>(Wqkv,  wp + OFF_QKV,  CC, 3 * CC);
    pack_w_kernel<<<(CC / 16) * (CC / 128),     256>>>(Wproj, wp + OFF_PROJ, CC, CC);
    pack_w_kernel<<<(CC / 16) * (4 * CC / 128), 256>>>(W1,    wp + OFF_W1,   CC, 4 * CC);
    pack_w_kernel<<<(4 * CC / 16) * (CC / 128), 256>>>(W2,    wp + OFF_W2,   4 * CC, CC);

    // 1. h = ln1(x)
    ln_kernel<<<NTOK, 256>>>(x, ln1_g, ln1_b, h);
    // 2. qkv = h @ Wqkv + bqkv
    tgemm_kernel<0><<<dim3(3 * CC / 128, NTOK / 128), 256, GEMM_SMEM>>>(
        h, wp + OFF_QKV, bqkv, nullptr, qkv, NTOK, 3 * CC, CC);
    // 3. y = causal_attention(qkv)
    attn_kernel<<<dim3(TT / 64, HH, BB), 256>>>(qkv, y);
    // 4. out = x + y @ Wproj + bproj
    tgemm_kernel<1><<<dim3(CC / 128, NTOK / 128), 256, GEMM_SMEM>>>(
        y, wp + OFF_PROJ, bproj, x, out, NTOK, CC, CC);
    // 5. h2 = ln2(out)
    ln_kernel<<<NTOK, 256>>>(out, ln2_g, ln2_b, h2);
    // 6. mid = relu(h2 @ W1 + b1)
    tgemm_kernel<2><<<dim3(4 * CC / 128, NTOK / 128), 256, GEMM_SMEM>>>(
        h2, wp + OFF_W1, b1, nullptr, mid, NTOK, 4 * CC, CC);
    // 7. out = out + mid @ W2 + b2
    tgemm_kernel<1><<<dim3(CC / 128, NTOK / 128), 256, GEMM_SMEM>>>(
        mid, wp + OFF_W2, b2, out, out, NTOK, CC, 4 * CC);
}

// round 8
// speedup vs baseline: 1.4032x; 1.4032x over previous
#include <cuda_runtime.h>
#include <cuda_fp16.h>
#include <cstdint>

// ---------------------------------------------------------------------------
// Problem constants
// ---------------------------------------------------------------------------
#define BB 8
#define TT 1024
#define CC 1024
#define HH 16
#define DD 64
#define NTOK (BB * TT)           // 8192
#define SCALE_ATTN 0.07216878364870323f  // 1/sqrt(3*C/H) = 1/sqrt(192)

// ---------------------------------------------------------------------------
// Scratch (device globals; no dynamic allocation allowed) — fp16 activations
// ---------------------------------------------------------------------------
__device__ __half g_h[NTOK * CC];          // ln1 out
__device__ __half g_qkv[NTOK * 3 * CC];    // qkv
__device__ __half g_y[NTOK * CC];          // attn out
__device__ __half g_h2[NTOK * CC];         // ln2 out
__device__ __half g_mid[NTOK * 4 * CC];    // mlp hidden
// transposed fp16 weights, [N][K] row-major
#define OFF_QKV  0
#define OFF_PROJ (3 * CC * CC)
#define OFF_W1   (OFF_PROJ + CC * CC)
#define OFF_W2   (OFF_W1 + 4 * CC * CC)
#define WP_TOTAL (OFF_W2 + 4 * CC * CC)
__device__ __half g_wt[WP_TOTAL];

// ---------------------------------------------------------------------------
// Helpers
// ---------------------------------------------------------------------------
__device__ __forceinline__ void mma_f16(float* c, const uint32_t* a, const uint32_t* b) {
    asm volatile(
        "mma.sync.aligned.m16n8k16.row.col.f32.f16.f16.f32 "
        "{%0,%1,%2,%3}, {%4,%5,%6,%7}, {%8,%9}, {%0,%1,%2,%3};"
        : "+f"(c[0]), "+f"(c[1]), "+f"(c[2]), "+f"(c[3])
        : "r"(a[0]), "r"(a[1]), "r"(a[2]), "r"(a[3]), "r"(b[0]), "r"(b[1]));
}

__device__ __forceinline__ void cp_async16(void* smem_ptr, const void* gptr) {
    uint32_t sp = (uint32_t)__cvta_generic_to_shared(smem_ptr);
    asm volatile("cp.async.ca.shared.global [%0], [%1], 16;" :: "r"(sp), "l"(gptr));
}

// ---------------------------------------------------------------------------
// Weight transpose + fp16 round: W[K][N] fp32 -> Wt[N][K] fp16
// ---------------------------------------------------------------------------
__global__ __launch_bounds__(256)
void transpose_w(const float* __restrict__ W, __half* __restrict__ Wt, int K, int N) {
    __shared__ float t[32][33];
    const int n0 = blockIdx.x * 32;
    const int k0 = blockIdx.y * 32;
    const int tx = threadIdx.x, ty = threadIdx.y;
    #pragma unroll
    for (int i = 0; i < 4; i++)
        t[ty + 8 * i][tx] = W[(size_t)(k0 + ty + 8 * i) * N + n0 + tx];
    __syncthreads();
    #pragma unroll
    for (int i = 0; i < 4; i++)
        Wt[(size_t)(n0 + ty + 8 * i) * K + k0 + tx] = __float2half_rn(t[tx][ty + 8 * i]);
}

// ---------------------------------------------------------------------------
// LayerNorm: one block per row; fp32 in -> fp16 out (feeds GEMM A).
// ---------------------------------------------------------------------------
__global__ __launch_bounds__(256)
void ln_kernel(const float* __restrict__ x, const float* __restrict__ g,
               const float* __restrict__ b, __half* __restrict__ out) {
    __shared__ float rs[8];
    __shared__ float rq[8];
    const int row = blockIdx.x;
    const float* xr = x + (size_t)row * CC;
    __half* yr = out + (size_t)row * CC;
    const int c = threadIdx.x * 4;

    float4 v = *(const float4*)(xr + c);
    float s  = v.x + v.y + v.z + v.w;
    float sq = v.x * v.x + v.y * v.y + v.z * v.z + v.w * v.w;
    #pragma unroll
    for (int o = 16; o; o >>= 1) {
        s  += __shfl_xor_sync(0xffffffffu, s, o);
        sq += __shfl_xor_sync(0xffffffffu, sq, o);
    }
    if ((threadIdx.x & 31) == 0) { rs[threadIdx.x >> 5] = s; rq[threadIdx.x >> 5] = sq; }
    __syncthreads();
    s = 0.f; sq = 0.f;
    #pragma unroll
    for (int i = 0; i < 8; i++) { s += rs[i]; sq += rq[i]; }

    const float mean = s * (1.f / CC);
    const float var  = sq * (1.f / CC) - mean * mean;
    const float rstd = rsqrtf(var + 1e-5f);

    float4 g4 = *(const float4*)(g + c);
    float4 b4 = *(const float4*)(b + c);
    __half2 h0 = __floats2half2_rn((v.x - mean) * rstd * g4.x + b4.x,
                                   (v.y - mean) * rstd * g4.y + b4.y);
    __half2 h1 = __floats2half2_rn((v.z - mean) * rstd * g4.z + b4.z,
                                   (v.w - mean) * rstd * g4.w + b4.w);
    *(__half2*)(yr + c)     = h0;
    *(__half2*)(yr + c + 2) = h1;
}

// ---------------------------------------------------------------------------
// FP16 tensor GEMM: C[M,N] = A[M,K] @ Wt[N,K]^T + bias (+Res | relu)
// 128x128 CTA tile, BK=32, 4-stage cp.async, 8 warps (2m x 4n), warp 64x32,
// mma.m16n8k16.f16 with fp32 accumulate.
// Smem: A/B tiles [128][40] halfs (stride 40 -> conflict-free frag LDS.32).
// EPI: 0 = bias -> half, 1 = bias + residual -> float, 2 = bias + relu -> half
// ---------------------------------------------------------------------------
#define STAGES 4
#define TSTRIDE 40                    // halfs per row
#define TILE_HALFS (128 * TSTRIDE)    // 5120 halfs = 10240 B
#define STG_HALFS (2 * TILE_HALFS)    // A + B per stage
#define GEMM_SMEM (STAGES * STG_HALFS * 2)   // 81920 B

template <int EPI>
__global__ __launch_bounds__(256, 2)
void hgemm_kernel(const __half* __restrict__ A, const __half* __restrict__ B,
                  const float* __restrict__ bias, const float* __restrict__ Res,
                  void* __restrict__ Cout, int M, int N, int K) {
    extern __shared__ __half hsmem[];

    const int tid  = threadIdx.x;
    const int warp = tid >> 5;
    const int lane = tid & 31;
    const int gid  = lane >> 2;   // 0..7
    const int tig  = lane & 3;    // 0..3
    const int wm   = (warp >> 2) * 64;   // m offset (2 rows of warps)
    const int wn   = (warp & 3) * 32;    // n offset (4 cols of warps)
    const int m0   = blockIdx.y * 128;
    const int n0   = blockIdx.x * 128;
    const int NIT  = K >> 5;

    float acc[4][4][4];
    #pragma unroll
    for (int i = 0; i < 4; i++)
        #pragma unroll
        for (int j = 0; j < 4; j++)
            #pragma unroll
            for (int r = 0; r < 4; r++) acc[i][j][r] = 0.f;

    auto load_tile = [&](int it, int stage) {
        __half* dA = hsmem + stage * STG_HALFS;
        __half* dB = dA + TILE_HALFS;
        const int kbase = it * 32;
        #pragma unroll
        for (int s = 0; s < 2; s++) {
            const int seg = tid * 2 + s;          // 0..511
            const int r  = seg >> 2;              // 0..127
            const int kk = (seg & 3) << 3;        // 0,8,16,24
            cp_async16(dA + r * TSTRIDE + kk, A + (size_t)(m0 + r) * K + kbase + kk);
        }
        #pragma unroll
        for (int s = 0; s < 2; s++) {
            const int seg = tid * 2 + s;
            const int r  = seg >> 2;
            const int kk = (seg & 3) << 3;
            cp_async16(dB + r * TSTRIDE + kk, B + (size_t)(n0 + r) * K + kbase + kk);
        }
        asm volatile("cp.async.commit_group;");
    };

    load_tile(0, 0);
    load_tile(1, 1);
    load_tile(2, 2);

    for (int it = 0; it < NIT; it++) {
        const int stage = it & (STAGES - 1);
        asm volatile("cp.async.wait_group %0;" :: "n"(STAGES - 2));
        __syncthreads();

        if (it + STAGES - 1 < NIT) load_tile(it + STAGES - 1, (it + STAGES - 1) & (STAGES - 1));

        const uint32_t* uA = (const uint32_t*)(hsmem + stage * STG_HALFS);
        const uint32_t* uB = uA + TILE_HALFS / 2;
        // row stride in uint32 = TSTRIDE/2 = 20

        #pragma unroll
        for (int ks = 0; ks < 2; ks++) {
            const int kb = ks * 8 + tig;          // uint32 offset within row
            uint32_t af[4][4], bf[4][2];
            #pragma unroll
            for (int i = 0; i < 4; i++) {
                const int rb = wm + i * 16 + gid;
                af[i][0] = uA[rb * 20 + kb];
                af[i][1] = uA[(rb + 8) * 20 + kb];
                af[i][2] = uA[rb * 20 + kb + 4];
                af[i][3] = uA[(rb + 8) * 20 + kb + 4];
            }
            #pragma unroll
            for (int j = 0; j < 4; j++) {
                const int cb = wn + j * 8 + gid;
                bf[j][0] = uB[cb * 20 + kb];
                bf[j][1] = uB[cb * 20 + kb + 4];
            }
            #pragma unroll
            for (int i = 0; i < 4; i++)
                #pragma unroll
                for (int j = 0; j < 4; j++)
                    mma_f16(acc[i][j], af[i], bf[j]);
        }
        __syncthreads();
    }

    // epilogue: c0/c1 -> (row gid, cols 2tig,2tig+1); c2/c3 -> row gid+8
    #pragma unroll
    for (int i = 0; i < 4; i++) {
        #pragma unroll
        for (int half = 0; half < 2; half++) {
            const int r = m0 + wm + i * 16 + gid + half * 8;
            const size_t rowoff = (size_t)r * N;
            #pragma unroll
            for (int j = 0; j < 4; j++) {
                const int c = n0 + wn + j * 8 + tig * 2;
                float v0 = acc[i][j][half * 2 + 0] + bias[c];
                float v1 = acc[i][j][half * 2 + 1] + bias[c + 1];
                if (EPI == 1) {
                    float2 r2 = *(const float2*)(Res + rowoff + c);
                    v0 += r2.x; v1 += r2.y;
                    float2 o; o.x = v0; o.y = v1;
                    *(float2*)((float*)Cout + rowoff + c) = o;
                } else {
                    if (EPI == 2) { v0 = fmaxf(v0, 0.f); v1 = fmaxf(v1, 0.f); }
                    *(__half2*)((__half*)Cout + rowoff + c) = __floats2half2_rn(v0, v1);
                }
            }
        }
    }
}

// ---------------------------------------------------------------------------
// Causal flash attention, fp32 compute, fp16 qkv in / fp16 y out.
// Block = (q-tile 64, head, batch), 256 thr.
// ---------------------------------------------------------------------------
__global__ __launch_bounds__(256)
void attn_kernel(const __half* __restrict__ qkv, __half* __restrict__ y) {
    __shared__ __align__(16) float Qs[64][64];
    __shared__ __align__(16) float KPs[64][64];
    __shared__ __align__(16) float Vs[64][64];

    const int tid = threadIdx.x;
    const int qb = blockIdx.x;
    const int h  = blockIdx.y;
    const int b  = blockIdx.z;
    const int rg = tid >> 4;
    const int cg = tid & 15;

    const size_t base = (size_t)b * TT * (3 * CC) + (size_t)h * DD;

    // load Q (transposed, pre-scaled): 64 rows x 64 dims, 8 halfs per step
    for (int i = tid; i < 512; i += 256) {
        const int r = i >> 3;
        const int d0 = (i & 7) << 3;
        const __half2* src = (const __half2*)(qkv + base + (size_t)(qb * 64 + r) * (3 * CC) + d0);
        #pragma unroll
        for (int p = 0; p < 4; p++) {
            float2 f = __half22float2(src[p]);
            Qs[d0 + 2 * p + 0][r] = f.x * SCALE_ATTN;
            Qs[d0 + 2 * p + 1][r] = f.y * SCALE_ATTN;
        }
    }

    float m[4], l[4], acc[4][4];
    #pragma unroll
    for (int i = 0; i < 4; i++) {
        m[i] = -1e30f; l[i] = 0.f;
        #pragma unroll
        for (int j = 0; j < 4; j++) acc[i][j] = 0.f;
    }

    for (int kb = 0; kb <= qb; kb++) {
        __syncthreads();
        for (int i = tid; i < 512; i += 256) {
            const int c = i >> 3;
            const int d0 = (i & 7) << 3;
            const size_t kaddr = base + CC + (size_t)(kb * 64 + c) * (3 * CC) + d0;
            const __half2* ksrc = (const __half2*)(qkv + kaddr);
            const __half2* vsrc = (const __half2*)(qkv + kaddr + CC);
            #pragma unroll
            for (int p = 0; p < 4; p++) {
                float2 f = __half22float2(ksrc[p]);
                KPs[d0 + 2 * p + 0][c] = f.x;
                KPs[d0 + 2 * p + 1][c] = f.y;
                float2 g = __half22float2(vsrc[p]);
                Vs[c][d0 + 2 * p + 0] = g.x;
                Vs[c][d0 + 2 * p + 1] = g.y;
            }
        }
        __syncthreads();

        float s[4][4];
        #pragma unroll
        for (int i = 0; i < 4; i++)
            #pragma unroll
            for (int j = 0; j < 4; j++) s[i][j] = 0.f;

        #pragma unroll 8
        for (int d = 0; d < 64; d++) {
            float qa[4], kk[4];
            *(float4*)qa = *(const float4*)&Qs[d][rg << 2];
            *(float4*)kk = *(const float4*)&KPs[d][cg << 2];
            #pragma unroll
            for (int i = 0; i < 4; i++)
                #pragma unroll
                for (int j = 0; j < 4; j++)
                    s[i][j] = fmaf(qa[i], kk[j], s[i][j]);
        }

        if (kb == qb) {
            #pragma unroll
            for (int i = 0; i < 4; i++)
                #pragma unroll
                for (int j = 0; j < 4; j++)
                    if ((cg << 2) + j > (rg << 2) + i) s[i][j] = -1e30f;
        }

        float rmax[4], rsum[4], corr[4];
        #pragma unroll
        for (int i = 0; i < 4; i++)
            rmax[i] = fmaxf(fmaxf(s[i][0], s[i][1]), fmaxf(s[i][2], s[i][3]));
        #pragma unroll
        for (int o = 1; o < 16; o <<= 1)
            #pragma unroll
            for (int i = 0; i < 4; i++)
                rmax[i] = fmaxf(rmax[i], __shfl_xor_sync(0xffffffffu, rmax[i], o));
        #pragma unroll
        for (int i = 0; i < 4; i++) {
            const float mn = fmaxf(m[i], rmax[i]);
            corr[i] = __expf(m[i] - mn);
            m[i] = mn;
            rsum[i] = 0.f;
            #pragma unroll
            for (int j = 0; j < 4; j++) {
                s[i][j] = __expf(s[i][j] - mn);
                rsum[i] += s[i][j];
            }
        }
        #pragma unroll
        for (int o = 1; o < 16; o <<= 1)
            #pragma unroll
            for (int i = 0; i < 4; i++)
                rsum[i] += __shfl_xor_sync(0xffffffffu, rsum[i], o);
        #pragma unroll
        for (int i = 0; i < 4; i++) {
            l[i] = l[i] * corr[i] + rsum[i];
            #pragma unroll
            for (int j = 0; j < 4; j++) acc[i][j] *= corr[i];
        }

        __syncthreads();
        #pragma unroll
        for (int j = 0; j < 4; j++) {
            const int c = (cg << 2) + j;
            *(float4*)&KPs[c][rg << 2] = make_float4(s[0][j], s[1][j], s[2][j], s[3][j]);
        }
        __syncthreads();

        #pragma unroll 8
        for (int c = 0; c < 64; c++) {
            float p[4], vv[4];
            *(float4*)p  = *(const float4*)&KPs[c][rg << 2];
            *(float4*)vv = *(const float4*)&Vs[c][cg << 2];
            #pragma unroll
            for (int i = 0; i < 4; i++)
                #pragma unroll
                for (int j = 0; j < 4; j++)
                    acc[i][j] = fmaf(p[i], vv[j], acc[i][j]);
        }
    }

    #pragma unroll
    for (int i = 0; i < 4; i++) {
        const float inv = 1.f / l[i];
        const int r = (rg << 2) + i;
        const size_t off = ((size_t)(b * TT + qb * 64 + r)) * CC + h * DD + (cg << 2);
        *(__half2*)(y + off)     = __floats2half2_rn(acc[i][0] * inv, acc[i][1] * inv);
        *(__half2*)(y + off + 2) = __floats2half2_rn(acc[i][2] * inv, acc[i][3] * inv);
    }
}

// ---------------------------------------------------------------------------
// Launch
// ---------------------------------------------------------------------------
extern "C" void kernel_launch(void* const* d_in, const int* in_sizes, int n_in,
                              void* d_out, int out_size) {
    const float* x     = (const float*)d_in[0];
    const float* Wqkv  = (const float*)d_in[1];
    const float* bqkv  = (const float*)d_in[2];
    const float* Wproj = (const float*)d_in[3];
    const float* bproj = (const float*)d_in[4];
    const float* ln1_g = (const float*)d_in[5];
    const float* ln1_b = (const float*)d_in[6];
    const float* ln2_g = (const float*)d_in[7];
    const float* ln2_b = (const float*)d_in[8];
    const float* W1    = (const float*)d_in[9];
    const float* b1    = (const float*)d_in[10];
    const float* W2    = (const float*)d_in[11];
    const float* b2    = (const float*)d_in[12];
    float* out = (float*)d_out;

    __half *h, *qkv, *y, *h2, *mid, *wt;
    cudaGetSymbolAddress((void**)&h,   g_h);
    cudaGetSymbolAddress((void**)&qkv, g_qkv);
    cudaGetSymbolAddress((void**)&y,   g_y);
    cudaGetSymbolAddress((void**)&h2,  g_h2);
    cudaGetSymbolAddress((void**)&mid, g_mid);
    cudaGetSymbolAddress((void**)&wt,  g_wt);

    static int smem_set = 0;
    if (!smem_set) {
        cudaFuncSetAttribute(hgemm_kernel<0>, cudaFuncAttributeMaxDynamicSharedMemorySize, GEMM_SMEM);
        cudaFuncSetAttribute(hgemm_kernel<1>, cudaFuncAttributeMaxDynamicSharedMemorySize, GEMM_SMEM);
        cudaFuncSetAttribute(hgemm_kernel<2>, cudaFuncAttributeMaxDynamicSharedMemorySize, GEMM_SMEM);
        smem_set = 1;
    }

    // 0. transpose + fp16-round weights: Wt[N][K]
    transpose_w<<<dim3(3 * CC / 32, CC / 32), dim3(32, 8)>>>(Wqkv,  wt + OFF_QKV,  CC, 3 * CC);
    transpose_w<<<dim3(CC / 32, CC / 32),     dim3(32, 8)>>>(Wproj, wt + OFF_PROJ, CC, CC);
    transpose_w<<<dim3(4 * CC / 32, CC / 32), dim3(32, 8)>>>(W1,    wt + OFF_W1,   CC, 4 * CC);
    transpose_w<<<dim3(CC / 32, 4 * CC / 32), dim3(32, 8)>>>(W2,    wt + OFF_W2,   4 * CC, CC);

    // 1. h = ln1(x)
    ln_kernel<<<NTOK, 256>>>(x, ln1_g, ln1_b, h);
    // 2. qkv = h @ Wqkv + bqkv   (half out)
    hgemm_kernel<0><<<dim3(3 * CC / 128, NTOK / 128), 256, GEMM_SMEM>>>(
        h, wt + OFF_QKV, bqkv, nullptr, qkv, NTOK, 3 * CC, CC);
    // 3. y = causal_attention(qkv)
    attn_kernel<<<dim3(TT / 64, HH, BB), 256>>>(qkv, y);
    // 4. out = x + y @ Wproj + bproj   (float out)
    hgemm_kernel<1><<<dim3(CC / 128, NTOK / 128), 256, GEMM_SMEM>>>(
        y, wt + OFF_PROJ, bproj, x, out, NTOK, CC, CC);
    // 5. h2 = ln2(out)
    ln_kernel<<<NTOK, 256>>>(out, ln2_g, ln2_b, h2);
    // 6. mid = relu(h2 @ W1 + b1)   (half out)
    hgemm_kernel<2><<<dim3(4 * CC / 128, NTOK / 128), 256, GEMM_SMEM>>>(
        h2, wt + OFF_W1, b1, nullptr, mid, NTOK, 4 * CC, CC);
    // 7. out = out + mid @ W2 + b2   (float out, K=4096)
    hgemm_kernel<1><<<dim3(CC / 128, NTOK / 128), 256, GEMM_SMEM>>>(
        mid, wt + OFF_W2, b2, out, out, NTOK, CC, 4 * CC);
}

// round 9
// speedup vs baseline: 2.5076x; 1.7870x over previous
#include <cuda_runtime.h>
#include <cuda_fp16.h>
#include <cstdint>

// ---------------------------------------------------------------------------
// Problem constants
// ---------------------------------------------------------------------------
#define BB 8
#define TT 1024
#define CC 1024
#define HH 16
#define DD 64
#define NTOK (BB * TT)           // 8192
#define SCALE_ATTN 0.07216878364870323f  // 1/sqrt(3*C/H) = 1/sqrt(192)

// ---------------------------------------------------------------------------
// Scratch (device globals) — fp16 activations
// ---------------------------------------------------------------------------
__device__ __half g_h[NTOK * CC];          // ln1 out
__device__ __half g_qkv[NTOK * 3 * CC];    // qkv
__device__ __half g_y[NTOK * CC];          // attn out
__device__ __half g_h2[NTOK * CC];         // ln2 out
__device__ __half g_mid[NTOK * 4 * CC];    // mlp hidden
// transposed fp16 weights, [N][K] row-major
#define OFF_QKV  0
#define OFF_PROJ (3 * CC * CC)
#define OFF_W1   (OFF_PROJ + CC * CC)
#define OFF_W2   (OFF_W1 + 4 * CC * CC)
#define WP_TOTAL (OFF_W2 + 4 * CC * CC)
__device__ __half g_wt[WP_TOTAL];

// ---------------------------------------------------------------------------
// Helpers
// ---------------------------------------------------------------------------
__device__ __forceinline__ void mma_f16(float* c, const uint32_t* a, const uint32_t* b) {
    asm volatile(
        "mma.sync.aligned.m16n8k16.row.col.f32.f16.f16.f32 "
        "{%0,%1,%2,%3}, {%4,%5,%6,%7}, {%8,%9}, {%0,%1,%2,%3};"
        : "+f"(c[0]), "+f"(c[1]), "+f"(c[2]), "+f"(c[3])
        : "r"(a[0]), "r"(a[1]), "r"(a[2]), "r"(a[3]), "r"(b[0]), "r"(b[1]));
}

__device__ __forceinline__ void cp_async16(void* smem_ptr, const void* gptr) {
    uint32_t sp = (uint32_t)__cvta_generic_to_shared(smem_ptr);
    asm volatile("cp.async.ca.shared.global [%0], [%1], 16;" :: "r"(sp), "l"(gptr));
}

__device__ __forceinline__ uint32_t smem_u32(const void* p) {
    return (uint32_t)__cvta_generic_to_shared(p);
}

__device__ __forceinline__ void ldsm4(uint32_t* r, uint32_t a) {
    asm volatile("ldmatrix.sync.aligned.m8n8.x4.shared.b16 {%0,%1,%2,%3}, [%4];"
        : "=r"(r[0]), "=r"(r[1]), "=r"(r[2]), "=r"(r[3]) : "r"(a));
}
__device__ __forceinline__ void ldsm4t(uint32_t* r, uint32_t a) {
    asm volatile("ldmatrix.sync.aligned.m8n8.x4.trans.shared.b16 {%0,%1,%2,%3}, [%4];"
        : "=r"(r[0]), "=r"(r[1]), "=r"(r[2]), "=r"(r[3]) : "r"(a));
}

__device__ __forceinline__ uint32_t h2bits(float a, float b) {
    __half2 h = __floats2half2_rn(a, b);
    return *reinterpret_cast<uint32_t*>(&h);
}

// ---------------------------------------------------------------------------
// Weight transpose + fp16 round: W[K][N] fp32 -> Wt[N][K] fp16
// ---------------------------------------------------------------------------
__global__ __launch_bounds__(256)
void transpose_w(const float* __restrict__ W, __half* __restrict__ Wt, int K, int N) {
    __shared__ float t[32][33];
    const int n0 = blockIdx.x * 32;
    const int k0 = blockIdx.y * 32;
    const int tx = threadIdx.x, ty = threadIdx.y;
    #pragma unroll
    for (int i = 0; i < 4; i++)
        t[ty + 8 * i][tx] = W[(size_t)(k0 + ty + 8 * i) * N + n0 + tx];
    __syncthreads();
    #pragma unroll
    for (int i = 0; i < 4; i++)
        Wt[(size_t)(n0 + ty + 8 * i) * K + k0 + tx] = __float2half_rn(t[tx][ty + 8 * i]);
}

// ---------------------------------------------------------------------------
// LayerNorm: one block per row; fp32 in -> fp16 out
// ---------------------------------------------------------------------------
__global__ __launch_bounds__(256)
void ln_kernel(const float* __restrict__ x, const float* __restrict__ g,
               const float* __restrict__ b, __half* __restrict__ out) {
    __shared__ float rs[8];
    __shared__ float rq[8];
    const int row = blockIdx.x;
    const float* xr = x + (size_t)row * CC;
    __half* yr = out + (size_t)row * CC;
    const int c = threadIdx.x * 4;

    float4 v = *(const float4*)(xr + c);
    float s  = v.x + v.y + v.z + v.w;
    float sq = v.x * v.x + v.y * v.y + v.z * v.z + v.w * v.w;
    #pragma unroll
    for (int o = 16; o; o >>= 1) {
        s  += __shfl_xor_sync(0xffffffffu, s, o);
        sq += __shfl_xor_sync(0xffffffffu, sq, o);
    }
    if ((threadIdx.x & 31) == 0) { rs[threadIdx.x >> 5] = s; rq[threadIdx.x >> 5] = sq; }
    __syncthreads();
    s = 0.f; sq = 0.f;
    #pragma unroll
    for (int i = 0; i < 8; i++) { s += rs[i]; sq += rq[i]; }

    const float mean = s * (1.f / CC);
    const float var  = sq * (1.f / CC) - mean * mean;
    const float rstd = rsqrtf(var + 1e-5f);

    float4 g4 = *(const float4*)(g + c);
    float4 b4 = *(const float4*)(b + c);
    *(__half2*)(yr + c)     = __floats2half2_rn((v.x - mean) * rstd * g4.x + b4.x,
                                                (v.y - mean) * rstd * g4.y + b4.y);
    *(__half2*)(yr + c + 2) = __floats2half2_rn((v.z - mean) * rstd * g4.z + b4.z,
                                                (v.w - mean) * rstd * g4.w + b4.w);
}

// ---------------------------------------------------------------------------
// FP16 tensor GEMM: C[M,N] = A[M,K] @ Wt[N,K]^T + bias (+Res | relu)
// 128x128 CTA tile, BK=32, 4-stage cp.async, 8 warps (2m x 4n), warp 64x32,
// ldmatrix fragment feed (stride-40 layout is ldsm conflict-free).
// EPI: 0 = bias -> half, 1 = bias + residual -> float, 2 = bias + relu -> half
// ---------------------------------------------------------------------------
#define STAGES 4
#define TSTRIDE 40                    // halfs per row
#define TILE_HALFS (128 * TSTRIDE)    // 5120 halfs = 10240 B
#define STG_HALFS (2 * TILE_HALFS)
#define GEMM_SMEM (STAGES * STG_HALFS * 2)   // 81920 B

template <int EPI>
__global__ __launch_bounds__(256, 2)
void hgemm_kernel(const __half* __restrict__ A, const __half* __restrict__ B,
                  const float* __restrict__ bias, const float* __restrict__ Res,
                  void* __restrict__ Cout, int M, int N, int K) {
    extern __shared__ __half hsmem[];

    const int tid  = threadIdx.x;
    const int warp = tid >> 5;
    const int lane = tid & 31;
    const int gid  = lane >> 2;
    const int tig  = lane & 3;
    const int part = lane >> 3, pr = lane & 7;
    const int wm   = (warp >> 2) * 64;   // m offset
    const int wn   = (warp & 3) * 32;    // n offset
    const int m0   = blockIdx.y * 128;
    const int n0   = blockIdx.x * 128;
    const int NIT  = K >> 5;

    float acc[4][4][4];
    #pragma unroll
    for (int i = 0; i < 4; i++)
        #pragma unroll
        for (int j = 0; j < 4; j++)
            #pragma unroll
            for (int r = 0; r < 4; r++) acc[i][j][r] = 0.f;

    auto load_tile = [&](int it, int stage) {
        __half* dA = hsmem + stage * STG_HALFS;
        __half* dB = dA + TILE_HALFS;
        const int kbase = it * 32;
        #pragma unroll
        for (int s = 0; s < 2; s++) {
            const int seg = tid * 2 + s;
            const int r  = seg >> 2;
            const int kk = (seg & 3) << 3;
            cp_async16(dA + r * TSTRIDE + kk, A + (size_t)(m0 + r) * K + kbase + kk);
        }
        #pragma unroll
        for (int s = 0; s < 2; s++) {
            const int seg = tid * 2 + s;
            const int r  = seg >> 2;
            const int kk = (seg & 3) << 3;
            cp_async16(dB + r * TSTRIDE + kk, B + (size_t)(n0 + r) * K + kbase + kk);
        }
        asm volatile("cp.async.commit_group;");
    };

    load_tile(0, 0);
    load_tile(1, 1);
    load_tile(2, 2);

    for (int it = 0; it < NIT; it++) {
        const int stage = it & (STAGES - 1);
        asm volatile("cp.async.wait_group %0;" :: "n"(STAGES - 2));
        __syncthreads();

        if (it + STAGES - 1 < NIT) load_tile(it + STAGES - 1, (it + STAGES - 1) & (STAGES - 1));

        const __half* hA = hsmem + stage * STG_HALFS;
        const __half* hB = hA + TILE_HALFS;

        #pragma unroll
        for (int ks = 0; ks < 2; ks++) {
            uint32_t af[4][4], bf[2][4];
            #pragma unroll
            for (int i = 0; i < 4; i++)
                ldsm4(af[i], smem_u32(
                    &hA[(wm + 16 * i + (part & 1) * 8 + pr) * TSTRIDE + 16 * ks + (part >> 1) * 8]));
            #pragma unroll
            for (int j2 = 0; j2 < 2; j2++)
                ldsm4(bf[j2], smem_u32(
                    &hB[(wn + 8 * (2 * j2 + (part >> 1)) + pr) * TSTRIDE + 16 * ks + (part & 1) * 8]));
            #pragma unroll
            for (int i = 0; i < 4; i++)
                #pragma unroll
                for (int j = 0; j < 4; j++)
                    mma_f16(acc[i][j], af[i], bf[j >> 1] + (j & 1) * 2);
        }
        __syncthreads();
    }

    // epilogue
    #pragma unroll
    for (int i = 0; i < 4; i++) {
        #pragma unroll
        for (int half = 0; half < 2; half++) {
            const int r = m0 + wm + i * 16 + gid + half * 8;
            const size_t rowoff = (size_t)r * N;
            #pragma unroll
            for (int j = 0; j < 4; j++) {
                const int c = n0 + wn + j * 8 + tig * 2;
                float v0 = acc[i][j][half * 2 + 0] + bias[c];
                float v1 = acc[i][j][half * 2 + 1] + bias[c + 1];
                if (EPI == 1) {
                    float2 r2 = *(const float2*)(Res + rowoff + c);
                    v0 += r2.x; v1 += r2.y;
                    float2 o; o.x = v0; o.y = v1;
                    *(float2*)((float*)Cout + rowoff + c) = o;
                } else {
                    if (EPI == 2) { v0 = fmaxf(v0, 0.f); v1 = fmaxf(v1, 0.f); }
                    *(__half2*)((__half*)Cout + rowoff + c) = __floats2half2_rn(v0, v1);
                }
            }
        }
    }
}

// ---------------------------------------------------------------------------
// Tensor-core causal flash attention (FA2-style, m16n8k16).
// Block = (q-tile 64, head, batch), 128 threads (4 warps, 16 q-rows each).
// Q frags in registers; K via ldmatrix; V via ldmatrix.trans; P stays in
// registers (S C-frag layout == PV A-frag layout). fp32 softmax/accum.
// ---------------------------------------------------------------------------
#define ASTR 72

__global__ __launch_bounds__(128)
void attn_kernel(const __half* __restrict__ qkv, __half* __restrict__ y) {
    __shared__ __half sQ[64][ASTR];
    __shared__ __half sK[2][64][ASTR];
    __shared__ __half sV[2][64][ASTR];

    const int tid  = threadIdx.x;
    const int warp = tid >> 5, lane = tid & 31;
    const int gid  = lane >> 2, tig = lane & 3;
    const int part = lane >> 3, pr = lane & 7;
    const int qb = blockIdx.x, h = blockIdx.y, b = blockIdx.z;
    const size_t base = (size_t)b * TT * (3 * CC) + (size_t)h * DD;

    // issue Q + KV(0) loads (group 0)
    #pragma unroll
    for (int i = 0; i < 4; i++) {
        const int seg = i * 128 + tid;          // 0..511
        const int r = seg >> 3, c8 = (seg & 7) << 3;
        cp_async16(&sQ[r][c8], qkv + base + (size_t)(qb * 64 + r) * (3 * CC) + c8);
    }
    #pragma unroll
    for (int i = 0; i < 4; i++) {
        const int seg = i * 128 + tid;
        const int r = seg >> 3, c8 = (seg & 7) << 3;
        const size_t ka = base + CC + (size_t)r * (3 * CC) + c8;
        cp_async16(&sK[0][r][c8], qkv + ka);
        cp_async16(&sV[0][r][c8], qkv + ka + CC);
    }
    asm volatile("cp.async.commit_group;");

    float o[8][4];
    #pragma unroll
    for (int j = 0; j < 8; j++)
        #pragma unroll
        for (int r = 0; r < 4; r++) o[j][r] = 0.f;
    float m0 = -1e30f, m1 = -1e30f, l0 = 0.f, l1 = 0.f;
    uint32_t qf[4][4];

    for (int kb = 0; kb <= qb; kb++) {
        const int buf = kb & 1;
        if (kb < qb) {
            #pragma unroll
            for (int i = 0; i < 4; i++) {
                const int seg = i * 128 + tid;
                const int r = seg >> 3, c8 = (seg & 7) << 3;
                const size_t ka = base + CC + (size_t)((kb + 1) * 64 + r) * (3 * CC) + c8;
                cp_async16(&sK[buf ^ 1][r][c8], qkv + ka);
                cp_async16(&sV[buf ^ 1][r][c8], qkv + ka + CC);
            }
            asm volatile("cp.async.commit_group;");
            asm volatile("cp.async.wait_group 1;");
        } else {
            asm volatile("cp.async.wait_group 0;");
        }
        __syncthreads();

        if (kb == 0) {
            #pragma unroll
            for (int ks = 0; ks < 4; ks++)
                ldsm4(qf[ks], smem_u32(
                    &sQ[16 * warp + (part & 1) * 8 + pr][16 * ks + (part >> 1) * 8]));
        }

        // --- S = Q K^T ---
        float s[8][4];
        #pragma unroll
        for (int j = 0; j < 8; j++)
            #pragma unroll
            for (int r = 0; r < 4; r++) s[j][r] = 0.f;

        #pragma unroll
        for (int ks = 0; ks < 4; ks++) {
            #pragma unroll
            for (int j2 = 0; j2 < 8; j2 += 2) {
                uint32_t kf[4];
                ldsm4(kf, smem_u32(
                    &sK[buf][8 * (j2 + (part >> 1)) + pr][16 * ks + (part & 1) * 8]));
                mma_f16(s[j2],     qf[ks], kf);
                mma_f16(s[j2 + 1], qf[ks], kf + 2);
            }
        }

        // scale + causal mask
        #pragma unroll
        for (int j = 0; j < 8; j++)
            #pragma unroll
            for (int r = 0; r < 4; r++) s[j][r] *= SCALE_ATTN;

        if (kb == qb) {
            const int r0 = 16 * warp + gid, r1 = r0 + 8;
            #pragma unroll
            for (int j = 0; j < 8; j++) {
                const int c0 = 8 * j + 2 * tig;
                if (c0     > r0) s[j][0] = -1e30f;
                if (c0 + 1 > r0) s[j][1] = -1e30f;
                if (c0     > r1) s[j][2] = -1e30f;
                if (c0 + 1 > r1) s[j][3] = -1e30f;
            }
        }

        // --- online softmax (rows gid, gid+8; reduce over 4 tig lanes) ---
        float mx0 = -1e30f, mx1 = -1e30f;
        #pragma unroll
        for (int j = 0; j < 8; j++) {
            mx0 = fmaxf(mx0, fmaxf(s[j][0], s[j][1]));
            mx1 = fmaxf(mx1, fmaxf(s[j][2], s[j][3]));
        }
        mx0 = fmaxf(mx0, __shfl_xor_sync(0xffffffffu, mx0, 1));
        mx0 = fmaxf(mx0, __shfl_xor_sync(0xffffffffu, mx0, 2));
        mx1 = fmaxf(mx1, __shfl_xor_sync(0xffffffffu, mx1, 1));
        mx1 = fmaxf(mx1, __shfl_xor_sync(0xffffffffu, mx1, 2));

        const float mn0 = fmaxf(m0, mx0), mn1 = fmaxf(m1, mx1);
        const float cr0 = __expf(m0 - mn0), cr1 = __expf(m1 - mn1);
        m0 = mn0; m1 = mn1;

        float rs0 = 0.f, rs1 = 0.f;
        #pragma unroll
        for (int j = 0; j < 8; j++) {
            s[j][0] = __expf(s[j][0] - mn0);
            s[j][1] = __expf(s[j][1] - mn0);
            rs0 += s[j][0] + s[j][1];
            s[j][2] = __expf(s[j][2] - mn1);
            s[j][3] = __expf(s[j][3] - mn1);
            rs1 += s[j][2] + s[j][3];
        }
        rs0 += __shfl_xor_sync(0xffffffffu, rs0, 1);
        rs0 += __shfl_xor_sync(0xffffffffu, rs0, 2);
        rs1 += __shfl_xor_sync(0xffffffffu, rs1, 1);
        rs1 += __shfl_xor_sync(0xffffffffu, rs1, 2);
        l0 = l0 * cr0 + rs0;
        l1 = l1 * cr1 + rs1;
        #pragma unroll
        for (int j = 0; j < 8; j++) {
            o[j][0] *= cr0; o[j][1] *= cr0;
            o[j][2] *= cr1; o[j][3] *= cr1;
        }

        // --- O += P V ---
        #pragma unroll
        for (int kk = 0; kk < 4; kk++) {
            uint32_t pa[4];
            pa[0] = h2bits(s[2 * kk][0],     s[2 * kk][1]);
            pa[1] = h2bits(s[2 * kk][2],     s[2 * kk][3]);
            pa[2] = h2bits(s[2 * kk + 1][0], s[2 * kk + 1][1]);
            pa[3] = h2bits(s[2 * kk + 1][2], s[2 * kk + 1][3]);
            #pragma unroll
            for (int jd = 0; jd < 8; jd += 2) {
                uint32_t vf[4];
                ldsm4t(vf, smem_u32(
                    &sV[buf][16 * kk + (part & 1) * 8 + pr][8 * (jd + (part >> 1))]));
                mma_f16(o[jd],     pa, vf);
                mma_f16(o[jd + 1], pa, vf + 2);
            }
        }
        __syncthreads();
    }

    // --- finalize; y in [B, T, H*D] ---
    const float i0 = 1.f / l0, i1 = 1.f / l1;
    const int r0 = qb * 64 + 16 * warp + gid;
    #pragma unroll
    for (int j = 0; j < 8; j++) {
        const int col = h * DD + 8 * j + 2 * tig;
        *(__half2*)(y + (size_t)(b * TT + r0) * CC + col) =
            __floats2half2_rn(o[j][0] * i0, o[j][1] * i0);
        *(__half2*)(y + (size_t)(b * TT + r0 + 8) * CC + col) =
            __floats2half2_rn(o[j][2] * i1, o[j][3] * i1);
    }
}

// ---------------------------------------------------------------------------
// Launch
// ---------------------------------------------------------------------------
extern "C" void kernel_launch(void* const* d_in, const int* in_sizes, int n_in,
                              void* d_out, int out_size) {
    const float* x     = (const float*)d_in[0];
    const float* Wqkv  = (const float*)d_in[1];
    const float* bqkv  = (const float*)d_in[2];
    const float* Wproj = (const float*)d_in[3];
    const float* bproj = (const float*)d_in[4];
    const float* ln1_g = (const float*)d_in[5];
    const float* ln1_b = (const float*)d_in[6];
    const float* ln2_g = (const float*)d_in[7];
    const float* ln2_b = (const float*)d_in[8];
    const float* W1    = (const float*)d_in[9];
    const float* b1    = (const float*)d_in[10];
    const float* W2    = (const float*)d_in[11];
    const float* b2    = (const float*)d_in[12];
    float* out = (float*)d_out;

    __half *h, *qkv, *y, *h2, *mid, *wt;
    cudaGetSymbolAddress((void**)&h,   g_h);
    cudaGetSymbolAddress((void**)&qkv, g_qkv);
    cudaGetSymbolAddress((void**)&y,   g_y);
    cudaGetSymbolAddress((void**)&h2,  g_h2);
    cudaGetSymbolAddress((void**)&mid, g_mid);
    cudaGetSymbolAddress((void**)&wt,  g_wt);

    static int smem_set = 0;
    if (!smem_set) {
        cudaFuncSetAttribute(hgemm_kernel<0>, cudaFuncAttributeMaxDynamicSharedMemorySize, GEMM_SMEM);
        cudaFuncSetAttribute(hgemm_kernel<1>, cudaFuncAttributeMaxDynamicSharedMemorySize, GEMM_SMEM);
        cudaFuncSetAttribute(hgemm_kernel<2>, cudaFuncAttributeMaxDynamicSharedMemorySize, GEMM_SMEM);
        smem_set = 1;
    }

    // 0. transpose + fp16-round weights: Wt[N][K]
    transpose_w<<<dim3(3 * CC / 32, CC / 32), dim3(32, 8)>>>(Wqkv,  wt + OFF_QKV,  CC, 3 * CC);
    transpose_w<<<dim3(CC / 32, CC / 32),     dim3(32, 8)>>>(Wproj, wt + OFF_PROJ, CC, CC);
    transpose_w<<<dim3(4 * CC / 32, CC / 32), dim3(32, 8)>>>(W1,    wt + OFF_W1,   CC, 4 * CC);
    transpose_w<<<dim3(CC / 32, 4 * CC / 32), dim3(32, 8)>>>(W2,    wt + OFF_W2,   4 * CC, CC);

    // 1. h = ln1(x)
    ln_kernel<<<NTOK, 256>>>(x, ln1_g, ln1_b, h);
    // 2. qkv = h @ Wqkv + bqkv   (half out)
    hgemm_kernel<0><<<dim3(3 * CC / 128, NTOK / 128), 256, GEMM_SMEM>>>(
        h, wt + OFF_QKV, bqkv, nullptr, qkv, NTOK, 3 * CC, CC);
    // 3. y = causal_attention(qkv)   (tensor-core FA)
    attn_kernel<<<dim3(TT / 64, HH, BB), 128>>>(qkv, y);
    // 4. out = x + y @ Wproj + bproj   (float out)
    hgemm_kernel<1><<<dim3(CC / 128, NTOK / 128), 256, GEMM_SMEM>>>(
        y, wt + OFF_PROJ, bproj, x, out, NTOK, CC, CC);
    // 5. h2 = ln2(out)
    ln_kernel<<<NTOK, 256>>>(out, ln2_g, ln2_b, h2);
    // 6. mid = relu(h2 @ W1 + b1)   (half out)
    hgemm_kernel<2><<<dim3(4 * CC / 128, NTOK / 128), 256, GEMM_SMEM>>>(
        h2, wt + OFF_W1, b1, nullptr, mid, NTOK, 4 * CC, CC);
    // 7. out = out + mid @ W2 + b2   (float out, K=4096)
    hgemm_kernel<1><<<dim3(CC / 128, NTOK / 128), 256, GEMM_SMEM>>>(
        mid, wt + OFF_W2, b2, out, out, NTOK, CC, 4 * CC);
}

// round 10
// speedup vs baseline: 2.6845x; 1.0706x over previous
#include <cuda_runtime.h>
#include <cuda_fp16.h>
#include <cstdint>

// ---------------------------------------------------------------------------
// Problem constants
// ---------------------------------------------------------------------------
#define BB 8
#define TT 1024
#define CC 1024
#define HH 16
#define DD 64
#define NTOK (BB * TT)           // 8192
#define SCALE_ATTN 0.07216878364870323f  // 1/sqrt(3*C/H) = 1/sqrt(192)

// ---------------------------------------------------------------------------
// Scratch (device globals) — fp16 activations
// ---------------------------------------------------------------------------
__device__ __half g_h[NTOK * CC];          // ln1 out
__device__ __half g_qkv[NTOK * 3 * CC];    // qkv
__device__ __half g_y[NTOK * CC];          // attn out
__device__ __half g_h2[NTOK * CC];         // ln2 out
__device__ __half g_mid[NTOK * 4 * CC];    // mlp hidden
// transposed fp16 weights, [N][K] row-major
#define OFF_QKV  0
#define OFF_PROJ (3 * CC * CC)
#define OFF_W1   (OFF_PROJ + CC * CC)
#define OFF_W2   (OFF_W1 + 4 * CC * CC)
#define WP_TOTAL (OFF_W2 + 4 * CC * CC)
__device__ __half g_wt[WP_TOTAL];

// ---------------------------------------------------------------------------
// Helpers
// ---------------------------------------------------------------------------
__device__ __forceinline__ void mma_f16(float* c, const uint32_t* a, const uint32_t* b) {
    asm volatile(
        "mma.sync.aligned.m16n8k16.row.col.f32.f16.f16.f32 "
        "{%0,%1,%2,%3}, {%4,%5,%6,%7}, {%8,%9}, {%0,%1,%2,%3};"
        : "+f"(c[0]), "+f"(c[1]), "+f"(c[2]), "+f"(c[3])
        : "r"(a[0]), "r"(a[1]), "r"(a[2]), "r"(a[3]), "r"(b[0]), "r"(b[1]));
}

__device__ __forceinline__ void cp_async16(void* smem_ptr, const void* gptr) {
    uint32_t sp = (uint32_t)__cvta_generic_to_shared(smem_ptr);
    asm volatile("cp.async.ca.shared.global [%0], [%1], 16;" :: "r"(sp), "l"(gptr));
}

__device__ __forceinline__ uint32_t smem_u32(const void* p) {
    return (uint32_t)__cvta_generic_to_shared(p);
}

__device__ __forceinline__ void ldsm4(uint32_t* r, uint32_t a) {
    asm volatile("ldmatrix.sync.aligned.m8n8.x4.shared.b16 {%0,%1,%2,%3}, [%4];"
        : "=r"(r[0]), "=r"(r[1]), "=r"(r[2]), "=r"(r[3]) : "r"(a));
}
__device__ __forceinline__ void ldsm4t(uint32_t* r, uint32_t a) {
    asm volatile("ldmatrix.sync.aligned.m8n8.x4.trans.shared.b16 {%0,%1,%2,%3}, [%4];"
        : "=r"(r[0]), "=r"(r[1]), "=r"(r[2]), "=r"(r[3]) : "r"(a));
}

__device__ __forceinline__ uint32_t h2bits(float a, float b) {
    __half2 h = __floats2half2_rn(a, b);
    return *reinterpret_cast<uint32_t*>(&h);
}

// ---------------------------------------------------------------------------
// Weight transpose + fp16 round: W[K][N] fp32 -> Wt[N][K] fp16
// ---------------------------------------------------------------------------
__global__ __launch_bounds__(256)
void transpose_w(const float* __restrict__ W, __half* __restrict__ Wt, int K, int N) {
    __shared__ float t[32][33];
    const int n0 = blockIdx.x * 32;
    const int k0 = blockIdx.y * 32;
    const int tx = threadIdx.x, ty = threadIdx.y;
    #pragma unroll
    for (int i = 0; i < 4; i++)
        t[ty + 8 * i][tx] = W[(size_t)(k0 + ty + 8 * i) * N + n0 + tx];
    __syncthreads();
    #pragma unroll
    for (int i = 0; i < 4; i++)
        Wt[(size_t)(n0 + ty + 8 * i) * K + k0 + tx] = __float2half_rn(t[tx][ty + 8 * i]);
}

// ---------------------------------------------------------------------------
// LayerNorm: one block per row; fp32 in -> fp16 out
// ---------------------------------------------------------------------------
__global__ __launch_bounds__(256)
void ln_kernel(const float* __restrict__ x, const float* __restrict__ g,
               const float* __restrict__ b, __half* __restrict__ out) {
    __shared__ float rs[8];
    __shared__ float rq[8];
    const int row = blockIdx.x;
    const float* xr = x + (size_t)row * CC;
    __half* yr = out + (size_t)row * CC;
    const int c = threadIdx.x * 4;

    float4 v = *(const float4*)(xr + c);
    float s  = v.x + v.y + v.z + v.w;
    float sq = v.x * v.x + v.y * v.y + v.z * v.z + v.w * v.w;
    #pragma unroll
    for (int o = 16; o; o >>= 1) {
        s  += __shfl_xor_sync(0xffffffffu, s, o);
        sq += __shfl_xor_sync(0xffffffffu, sq, o);
    }
    if ((threadIdx.x & 31) == 0) { rs[threadIdx.x >> 5] = s; rq[threadIdx.x >> 5] = sq; }
    __syncthreads();
    s = 0.f; sq = 0.f;
    #pragma unroll
    for (int i = 0; i < 8; i++) { s += rs[i]; sq += rq[i]; }

    const float mean = s * (1.f / CC);
    const float var  = sq * (1.f / CC) - mean * mean;
    const float rstd = rsqrtf(var + 1e-5f);

    float4 g4 = *(const float4*)(g + c);
    float4 b4 = *(const float4*)(b + c);
    *(__half2*)(yr + c)     = __floats2half2_rn((v.x - mean) * rstd * g4.x + b4.x,
                                                (v.y - mean) * rstd * g4.y + b4.y);
    *(__half2*)(yr + c + 2) = __floats2half2_rn((v.z - mean) * rstd * g4.z + b4.z,
                                                (v.w - mean) * rstd * g4.w + b4.w);
}

// ---------------------------------------------------------------------------
// FP16 tensor GEMM: C[M,N] = A[M,K] @ Wt[N,K]^T + bias (+Res | relu)
// CTA tile 256x128, BK=32, 4-stage cp.async, 8 warps (4m x 2n),
// warp tile 64x64 (8 ldsm.x4 : 64 mma per k16), ldmatrix feed,
// stride-40 conflict-free smem layout. 1 CTA/SM (high reg use).
// EPI: 0 = bias -> half, 1 = bias + residual -> float, 2 = bias + relu -> half
// ---------------------------------------------------------------------------
#define STAGES 4
#define TSTRIDE 40                       // halfs per row
#define A_HALFS (256 * TSTRIDE)          // 10240 halfs
#define B_HALFS (128 * TSTRIDE)          // 5120 halfs
#define STG_HALFS (A_HALFS + B_HALFS)    // 15360 halfs = 30720 B
#define GEMM_SMEM (STAGES * STG_HALFS * 2)   // 122880 B

template <int EPI>
__global__ __launch_bounds__(256, 1)
void hgemm_kernel(const __half* __restrict__ A, const __half* __restrict__ B,
                  const float* __restrict__ bias, const float* __restrict__ Res,
                  void* __restrict__ Cout, int M, int N, int K) {
    extern __shared__ __half hsmem[];

    const int tid  = threadIdx.x;
    const int warp = tid >> 5;
    const int lane = tid & 31;
    const int gid  = lane >> 2;
    const int tig  = lane & 3;
    const int part = lane >> 3, pr = lane & 7;
    const int wm   = (warp >> 1) * 64;   // m offset (4 warp-rows)
    const int wn   = (warp & 1) * 64;    // n offset (2 warp-cols)
    const int m0   = blockIdx.y * 256;
    const int n0   = blockIdx.x * 128;
    const int NIT  = K >> 5;

    float acc[4][8][4];
    #pragma unroll
    for (int i = 0; i < 4; i++)
        #pragma unroll
        for (int j = 0; j < 8; j++)
            #pragma unroll
            for (int r = 0; r < 4; r++) acc[i][j][r] = 0.f;

    auto load_tile = [&](int it, int stage) {
        __half* dA = hsmem + stage * STG_HALFS;
        __half* dB = dA + A_HALFS;
        const int kbase = it * 32;
        #pragma unroll
        for (int s = 0; s < 4; s++) {
            const int seg = s * 256 + tid;        // 0..1023
            const int r  = seg >> 2;              // 0..255
            const int kk = (seg & 3) << 3;        // 0,8,16,24
            cp_async16(dA + r * TSTRIDE + kk, A + (size_t)(m0 + r) * K + kbase + kk);
        }
        #pragma unroll
        for (int s = 0; s < 2; s++) {
            const int seg = s * 256 + tid;        // 0..511
            const int r  = seg >> 2;              // 0..127
            const int kk = (seg & 3) << 3;
            cp_async16(dB + r * TSTRIDE + kk, B + (size_t)(n0 + r) * K + kbase + kk);
        }
        asm volatile("cp.async.commit_group;");
    };

    load_tile(0, 0);
    load_tile(1, 1);
    load_tile(2, 2);

    for (int it = 0; it < NIT; it++) {
        const int stage = it & (STAGES - 1);
        asm volatile("cp.async.wait_group %0;" :: "n"(STAGES - 2));
        __syncthreads();

        if (it + STAGES - 1 < NIT) load_tile(it + STAGES - 1, (it + STAGES - 1) & (STAGES - 1));

        const __half* hA = hsmem + stage * STG_HALFS;
        const __half* hB = hA + A_HALFS;

        #pragma unroll
        for (int ks = 0; ks < 2; ks++) {
            uint32_t af[4][4], bf[4][4];
            #pragma unroll
            for (int i = 0; i < 4; i++)
                ldsm4(af[i], smem_u32(
                    &hA[(wm + 16 * i + (part & 1) * 8 + pr) * TSTRIDE + 16 * ks + (part >> 1) * 8]));
            #pragma unroll
            for (int j2 = 0; j2 < 4; j2++)
                ldsm4(bf[j2], smem_u32(
                    &hB[(wn + 8 * (2 * j2 + (part >> 1)) + pr) * TSTRIDE + 16 * ks + (part & 1) * 8]));
            #pragma unroll
            for (int i = 0; i < 4; i++)
                #pragma unroll
                for (int j = 0; j < 8; j++)
                    mma_f16(acc[i][j], af[i], bf[j >> 1] + (j & 1) * 2);
        }
        __syncthreads();
    }

    // epilogue
    #pragma unroll
    for (int i = 0; i < 4; i++) {
        #pragma unroll
        for (int half = 0; half < 2; half++) {
            const int r = m0 + wm + i * 16 + gid + half * 8;
            const size_t rowoff = (size_t)r * N;
            #pragma unroll
            for (int j = 0; j < 8; j++) {
                const int c = n0 + wn + j * 8 + tig * 2;
                float v0 = acc[i][j][half * 2 + 0] + bias[c];
                float v1 = acc[i][j][half * 2 + 1] + bias[c + 1];
                if (EPI == 1) {
                    float2 r2 = *(const float2*)(Res + rowoff + c);
                    v0 += r2.x; v1 += r2.y;
                    float2 o; o.x = v0; o.y = v1;
                    *(float2*)((float*)Cout + rowoff + c) = o;
                } else {
                    if (EPI == 2) { v0 = fmaxf(v0, 0.f); v1 = fmaxf(v1, 0.f); }
                    *(__half2*)((__half*)Cout + rowoff + c) = __floats2half2_rn(v0, v1);
                }
            }
        }
    }
}

// ---------------------------------------------------------------------------
// Tensor-core causal flash attention (FA2-style, m16n8k16). Unchanged from R8.
// ---------------------------------------------------------------------------
#define ASTR 72

__global__ __launch_bounds__(128)
void attn_kernel(const __half* __restrict__ qkv, __half* __restrict__ y) {
    __shared__ __half sQ[64][ASTR];
    __shared__ __half sK[2][64][ASTR];
    __shared__ __half sV[2][64][ASTR];

    const int tid  = threadIdx.x;
    const int warp = tid >> 5, lane = tid & 31;
    const int gid  = lane >> 2, tig = lane & 3;
    const int part = lane >> 3, pr = lane & 7;
    const int qb = blockIdx.x, h = blockIdx.y, b = blockIdx.z;
    const size_t base = (size_t)b * TT * (3 * CC) + (size_t)h * DD;

    #pragma unroll
    for (int i = 0; i < 4; i++) {
        const int seg = i * 128 + tid;
        const int r = seg >> 3, c8 = (seg & 7) << 3;
        cp_async16(&sQ[r][c8], qkv + base + (size_t)(qb * 64 + r) * (3 * CC) + c8);
    }
    #pragma unroll
    for (int i = 0; i < 4; i++) {
        const int seg = i * 128 + tid;
        const int r = seg >> 3, c8 = (seg & 7) << 3;
        const size_t ka = base + CC + (size_t)r * (3 * CC) + c8;
        cp_async16(&sK[0][r][c8], qkv + ka);
        cp_async16(&sV[0][r][c8], qkv + ka + CC);
    }
    asm volatile("cp.async.commit_group;");

    float o[8][4];
    #pragma unroll
    for (int j = 0; j < 8; j++)
        #pragma unroll
        for (int r = 0; r < 4; r++) o[j][r] = 0.f;
    float m0 = -1e30f, m1 = -1e30f, l0 = 0.f, l1 = 0.f;
    uint32_t qf[4][4];

    for (int kb = 0; kb <= qb; kb++) {
        const int buf = kb & 1;
        if (kb < qb) {
            #pragma unroll
            for (int i = 0; i < 4; i++) {
                const int seg = i * 128 + tid;
                const int r = seg >> 3, c8 = (seg & 7) << 3;
                const size_t ka = base + CC + (size_t)((kb + 1) * 64 + r) * (3 * CC) + c8;
                cp_async16(&sK[buf ^ 1][r][c8], qkv + ka);
                cp_async16(&sV[buf ^ 1][r][c8], qkv + ka + CC);
            }
            asm volatile("cp.async.commit_group;");
            asm volatile("cp.async.wait_group 1;");
        } else {
            asm volatile("cp.async.wait_group 0;");
        }
        __syncthreads();

        if (kb == 0) {
            #pragma unroll
            for (int ks = 0; ks < 4; ks++)
                ldsm4(qf[ks], smem_u32(
                    &sQ[16 * warp + (part & 1) * 8 + pr][16 * ks + (part >> 1) * 8]));
        }

        float s[8][4];
        #pragma unroll
        for (int j = 0; j < 8; j++)
            #pragma unroll
            for (int r = 0; r < 4; r++) s[j][r] = 0.f;

        #pragma unroll
        for (int ks = 0; ks < 4; ks++) {
            #pragma unroll
            for (int j2 = 0; j2 < 8; j2 += 2) {
                uint32_t kf[4];
                ldsm4(kf, smem_u32(
                    &sK[buf][8 * (j2 + (part >> 1)) + pr][16 * ks + (part & 1) * 8]));
                mma_f16(s[j2],     qf[ks], kf);
                mma_f16(s[j2 + 1], qf[ks], kf + 2);
            }
        }

        #pragma unroll
        for (int j = 0; j < 8; j++)
            #pragma unroll
            for (int r = 0; r < 4; r++) s[j][r] *= SCALE_ATTN;

        if (kb == qb) {
            const int r0 = 16 * warp + gid, r1 = r0 + 8;
            #pragma unroll
            for (int j = 0; j < 8; j++) {
                const int c0 = 8 * j + 2 * tig;
                if (c0     > r0) s[j][0] = -1e30f;
                if (c0 + 1 > r0) s[j][1] = -1e30f;
                if (c0     > r1) s[j][2] = -1e30f;
                if (c0 + 1 > r1) s[j][3] = -1e30f;
            }
        }

        float mx0 = -1e30f, mx1 = -1e30f;
        #pragma unroll
        for (int j = 0; j < 8; j++) {
            mx0 = fmaxf(mx0, fmaxf(s[j][0], s[j][1]));
            mx1 = fmaxf(mx1, fmaxf(s[j][2], s[j][3]));
        }
        mx0 = fmaxf(mx0, __shfl_xor_sync(0xffffffffu, mx0, 1));
        mx0 = fmaxf(mx0, __shfl_xor_sync(0xffffffffu, mx0, 2));
        mx1 = fmaxf(mx1, __shfl_xor_sync(0xffffffffu, mx1, 1));
        mx1 = fmaxf(mx1, __shfl_xor_sync(0xffffffffu, mx1, 2));

        const float mn0 = fmaxf(m0, mx0), mn1 = fmaxf(m1, mx1);
        const float cr0 = __expf(m0 - mn0), cr1 = __expf(m1 - mn1);
        m0 = mn0; m1 = mn1;

        float rs0 = 0.f, rs1 = 0.f;
        #pragma unroll
        for (int j = 0; j < 8; j++) {
            s[j][0] = __expf(s[j][0] - mn0);
            s[j][1] = __expf(s[j][1] - mn0);
            rs0 += s[j][0] + s[j][1];
            s[j][2] = __expf(s[j][2] - mn1);
            s[j][3] = __expf(s[j][3] - mn1);
            rs1 += s[j][2] + s[j][3];
        }
        rs0 += __shfl_xor_sync(0xffffffffu, rs0, 1);
        rs0 += __shfl_xor_sync(0xffffffffu, rs0, 2);
        rs1 += __shfl_xor_sync(0xffffffffu, rs1, 1);
        rs1 += __shfl_xor_sync(0xffffffffu, rs1, 2);
        l0 = l0 * cr0 + rs0;
        l1 = l1 * cr1 + rs1;
        #pragma unroll
        for (int j = 0; j < 8; j++) {
            o[j][0] *= cr0; o[j][1] *= cr0;
            o[j][2] *= cr1; o[j][3] *= cr1;
        }

        #pragma unroll
        for (int kk = 0; kk < 4; kk++) {
            uint32_t pa[4];
            pa[0] = h2bits(s[2 * kk][0],     s[2 * kk][1]);
            pa[1] = h2bits(s[2 * kk][2],     s[2 * kk][3]);
            pa[2] = h2bits(s[2 * kk + 1][0], s[2 * kk + 1][1]);
            pa[3] = h2bits(s[2 * kk + 1][2], s[2 * kk + 1][3]);
            #pragma unroll
            for (int jd = 0; jd < 8; jd += 2) {
                uint32_t vf[4];
                ldsm4t(vf, smem_u32(
                    &sV[buf][16 * kk + (part & 1) * 8 + pr][8 * (jd + (part >> 1))]));
                mma_f16(o[jd],     pa, vf);
                mma_f16(o[jd + 1], pa, vf + 2);
            }
        }
        __syncthreads();
    }

    const float i0 = 1.f / l0, i1 = 1.f / l1;
    const int r0 = qb * 64 + 16 * warp + gid;
    #pragma unroll
    for (int j = 0; j < 8; j++) {
        const int col = h * DD + 8 * j + 2 * tig;
        *(__half2*)(y + (size_t)(b * TT + r0) * CC + col) =
            __floats2half2_rn(o[j][0] * i0, o[j][1] * i0);
        *(__half2*)(y + (size_t)(b * TT + r0 + 8) * CC + col) =
            __floats2half2_rn(o[j][2] * i1, o[j][3] * i1);
    }
}

// ---------------------------------------------------------------------------
// Launch
// ---------------------------------------------------------------------------
extern "C" void kernel_launch(void* const* d_in, const int* in_sizes, int n_in,
                              void* d_out, int out_size) {
    const float* x     = (const float*)d_in[0];
    const float* Wqkv  = (const float*)d_in[1];
    const float* bqkv  = (const float*)d_in[2];
    const float* Wproj = (const float*)d_in[3];
    const float* bproj = (const float*)d_in[4];
    const float* ln1_g = (const float*)d_in[5];
    const float* ln1_b = (const float*)d_in[6];
    const float* ln2_g = (const float*)d_in[7];
    const float* ln2_b = (const float*)d_in[8];
    const float* W1    = (const float*)d_in[9];
    const float* b1    = (const float*)d_in[10];
    const float* W2    = (const float*)d_in[11];
    const float* b2    = (const float*)d_in[12];
    float* out = (float*)d_out;

    __half *h, *qkv, *y, *h2, *mid, *wt;
    cudaGetSymbolAddress((void**)&h,   g_h);
    cudaGetSymbolAddress((void**)&qkv, g_qkv);
    cudaGetSymbolAddress((void**)&y,   g_y);
    cudaGetSymbolAddress((void**)&h2,  g_h2);
    cudaGetSymbolAddress((void**)&mid, g_mid);
    cudaGetSymbolAddress((void**)&wt,  g_wt);

    static int smem_set = 0;
    if (!smem_set) {
        cudaFuncSetAttribute(hgemm_kernel<0>, cudaFuncAttributeMaxDynamicSharedMemorySize, GEMM_SMEM);
        cudaFuncSetAttribute(hgemm_kernel<1>, cudaFuncAttributeMaxDynamicSharedMemorySize, GEMM_SMEM);
        cudaFuncSetAttribute(hgemm_kernel<2>, cudaFuncAttributeMaxDynamicSharedMemorySize, GEMM_SMEM);
        smem_set = 1;
    }

    // 0. transpose + fp16-round weights: Wt[N][K]
    transpose_w<<<dim3(3 * CC / 32, CC / 32), dim3(32, 8)>>>(Wqkv,  wt + OFF_QKV,  CC, 3 * CC);
    transpose_w<<<dim3(CC / 32, CC / 32),     dim3(32, 8)>>>(Wproj, wt + OFF_PROJ, CC, CC);
    transpose_w<<<dim3(4 * CC / 32, CC / 32), dim3(32, 8)>>>(W1,    wt + OFF_W1,   CC, 4 * CC);
    transpose_w<<<dim3(CC / 32, 4 * CC / 32), dim3(32, 8)>>>(W2,    wt + OFF_W2,   4 * CC, CC);

    // 1. h = ln1(x)
    ln_kernel<<<NTOK, 256>>>(x, ln1_g, ln1_b, h);
    // 2. qkv = h @ Wqkv + bqkv   (half out)
    hgemm_kernel<0><<<dim3(3 * CC / 128, NTOK / 256), 256, GEMM_SMEM>>>(
        h, wt + OFF_QKV, bqkv, nullptr, qkv, NTOK, 3 * CC, CC);
    // 3. y = causal_attention(qkv)   (tensor-core FA)
    attn_kernel<<<dim3(TT / 64, HH, BB), 128>>>(qkv, y);
    // 4. out = x + y @ Wproj + bproj   (float out)
    hgemm_kernel<1><<<dim3(CC / 128, NTOK / 256), 256, GEMM_SMEM>>>(
        y, wt + OFF_PROJ, bproj, x, out, NTOK, CC, CC);
    // 5. h2 = ln2(out)
    ln_kernel<<<NTOK, 256>>>(out, ln2_g, ln2_b, h2);
    // 6. mid = relu(h2 @ W1 + b1)   (half out)
    hgemm_kernel<2><<<dim3(4 * CC / 128, NTOK / 256), 256, GEMM_SMEM>>>(
        h2, wt + OFF_W1, b1, nullptr, mid, NTOK, 4 * CC, CC);
    // 7. out = out + mid @ W2 + b2   (float out, K=4096)
    hgemm_kernel<1><<<dim3(CC / 128, NTOK / 256), 256, GEMM_SMEM>>>(
        mid, wt + OFF_W2, b2, out, out, NTOK, CC, 4 * CC);
}

// round 11
// speedup vs baseline: 3.2669x; 1.2170x over previous
#include <cuda_runtime.h>
#include <cuda_fp16.h>
#include <cstdint>

// ---------------------------------------------------------------------------
// Problem constants
// ---------------------------------------------------------------------------
#define BB 8
#define TT 1024
#define CC 1024
#define HH 16
#define DD 64
#define NTOK (BB * TT)           // 8192
#define SCALE_ATTN 0.07216878364870323f  // 1/sqrt(3*C/H) = 1/sqrt(192)

// ---------------------------------------------------------------------------
// Scratch (device globals) — fp16 activations
// ---------------------------------------------------------------------------
__device__ __half g_h[NTOK * CC];          // ln1 out
__device__ __half g_qkv[NTOK * 3 * CC];    // qkv
__device__ __half g_y[NTOK * CC];          // attn out
__device__ __half g_h2[NTOK * CC];         // ln2 out
__device__ __half g_mid[NTOK * 4 * CC];    // mlp hidden
// transposed fp16 weights, [N][K] row-major
#define OFF_QKV  0
#define OFF_PROJ (3 * CC * CC)
#define OFF_W1   (OFF_PROJ + CC * CC)
#define OFF_W2   (OFF_W1 + 4 * CC * CC)
#define WP_TOTAL (OFF_W2 + 4 * CC * CC)
__device__ __half g_wt[WP_TOTAL];

// ---------------------------------------------------------------------------
// Helpers
// ---------------------------------------------------------------------------
__device__ __forceinline__ void mma_f16(float* c, const uint32_t* a, const uint32_t* b) {
    asm volatile(
        "mma.sync.aligned.m16n8k16.row.col.f32.f16.f16.f32 "
        "{%0,%1,%2,%3}, {%4,%5,%6,%7}, {%8,%9}, {%0,%1,%2,%3};"
        : "+f"(c[0]), "+f"(c[1]), "+f"(c[2]), "+f"(c[3])
        : "r"(a[0]), "r"(a[1]), "r"(a[2]), "r"(a[3]), "r"(b[0]), "r"(b[1]));
}

__device__ __forceinline__ void cp_async16(void* smem_ptr, const void* gptr) {
    uint32_t sp = (uint32_t)__cvta_generic_to_shared(smem_ptr);
    asm volatile("cp.async.ca.shared.global [%0], [%1], 16;" :: "r"(sp), "l"(gptr));
}

__device__ __forceinline__ uint32_t smem_u32(const void* p) {
    return (uint32_t)__cvta_generic_to_shared(p);
}

__device__ __forceinline__ void ldsm4(uint32_t* r, uint32_t a) {
    asm volatile("ldmatrix.sync.aligned.m8n8.x4.shared.b16 {%0,%1,%2,%3}, [%4];"
        : "=r"(r[0]), "=r"(r[1]), "=r"(r[2]), "=r"(r[3]) : "r"(a));
}
__device__ __forceinline__ void ldsm4t(uint32_t* r, uint32_t a) {
    asm volatile("ldmatrix.sync.aligned.m8n8.x4.trans.shared.b16 {%0,%1,%2,%3}, [%4];"
        : "=r"(r[0]), "=r"(r[1]), "=r"(r[2]), "=r"(r[3]) : "r"(a));
}

__device__ __forceinline__ uint32_t h2bits(float a, float b) {
    __half2 h = __floats2half2_rn(a, b);
    return *reinterpret_cast<uint32_t*>(&h);
}

// ---------------------------------------------------------------------------
// Weight transpose + fp16 round: W[K][N] fp32 -> Wt[N][K] fp16
// ---------------------------------------------------------------------------
__global__ __launch_bounds__(256)
void transpose_w(const float* __restrict__ W, __half* __restrict__ Wt, int K, int N) {
    __shared__ float t[32][33];
    const int n0 = blockIdx.x * 32;
    const int k0 = blockIdx.y * 32;
    const int tx = threadIdx.x, ty = threadIdx.y;
    #pragma unroll
    for (int i = 0; i < 4; i++)
        t[ty + 8 * i][tx] = W[(size_t)(k0 + ty + 8 * i) * N + n0 + tx];
    __syncthreads();
    #pragma unroll
    for (int i = 0; i < 4; i++)
        Wt[(size_t)(n0 + ty + 8 * i) * K + k0 + tx] = __float2half_rn(t[tx][ty + 8 * i]);
}

// ---------------------------------------------------------------------------
// LayerNorm: one block per row; fp32 in -> fp16 out
// ---------------------------------------------------------------------------
__global__ __launch_bounds__(256)
void ln_kernel(const float* __restrict__ x, const float* __restrict__ g,
               const float* __restrict__ b, __half* __restrict__ out) {
    __shared__ float rs[8];
    __shared__ float rq[8];
    const int row = blockIdx.x;
    const float* xr = x + (size_t)row * CC;
    __half* yr = out + (size_t)row * CC;
    const int c = threadIdx.x * 4;

    float4 v = *(const float4*)(xr + c);
    float s  = v.x + v.y + v.z + v.w;
    float sq = v.x * v.x + v.y * v.y + v.z * v.z + v.w * v.w;
    #pragma unroll
    for (int o = 16; o; o >>= 1) {
        s  += __shfl_xor_sync(0xffffffffu, s, o);
        sq += __shfl_xor_sync(0xffffffffu, sq, o);
    }
    if ((threadIdx.x & 31) == 0) { rs[threadIdx.x >> 5] = s; rq[threadIdx.x >> 5] = sq; }
    __syncthreads();
    s = 0.f; sq = 0.f;
    #pragma unroll
    for (int i = 0; i < 8; i++) { s += rs[i]; sq += rq[i]; }

    const float mean = s * (1.f / CC);
    const float var  = sq * (1.f / CC) - mean * mean;
    const float rstd = rsqrtf(var + 1e-5f);

    float4 g4 = *(const float4*)(g + c);
    float4 b4 = *(const float4*)(b + c);
    *(__half2*)(yr + c)     = __floats2half2_rn((v.x - mean) * rstd * g4.x + b4.x,
                                                (v.y - mean) * rstd * g4.y + b4.y);
    *(__half2*)(yr + c + 2) = __floats2half2_rn((v.z - mean) * rstd * g4.z + b4.z,
                                                (v.w - mean) * rstd * g4.w + b4.w);
}

// ---------------------------------------------------------------------------
// FP16 tensor GEMM: C[M,N] = A[M,K] @ Wt[N,K]^T + bias (+Res | relu)
// CTA tile 256x128, BK=64, 3-stage cp.async, ONE sync per k-iter,
// 8 warps (4m x 2n), warp tile 64x64, ldmatrix feed, stride-72 layout.
// EPI: 0 = bias -> half, 1 = bias + residual -> float, 2 = bias + relu -> half
// ---------------------------------------------------------------------------
#define STAGES 3
#define TSTRIDE 72                       // halfs per row (BK=64 + pad 8)
#define A_HALFS (256 * TSTRIDE)          // 18432 halfs
#define B_HALFS (128 * TSTRIDE)          // 9216 halfs
#define STG_HALFS (A_HALFS + B_HALFS)    // 27648 halfs
#define GEMM_SMEM (STAGES * STG_HALFS * 2)   // 165888 B

template <int EPI>
__global__ __launch_bounds__(256, 1)
void hgemm_kernel(const __half* __restrict__ A, const __half* __restrict__ B,
                  const float* __restrict__ bias, const float* __restrict__ Res,
                  void* __restrict__ Cout, int M, int N, int K) {
    extern __shared__ __half hsmem[];

    const int tid  = threadIdx.x;
    const int warp = tid >> 5;
    const int lane = tid & 31;
    const int gid  = lane >> 2;
    const int tig  = lane & 3;
    const int part = lane >> 3, pr = lane & 7;
    const int wm   = (warp >> 1) * 64;   // m offset (4 warp-rows)
    const int wn   = (warp & 1) * 64;    // n offset (2 warp-cols)
    const int m0   = blockIdx.y * 256;
    const int n0   = blockIdx.x * 128;
    const int NIT  = K >> 6;

    float acc[4][8][4];
    #pragma unroll
    for (int i = 0; i < 4; i++)
        #pragma unroll
        for (int j = 0; j < 8; j++)
            #pragma unroll
            for (int r = 0; r < 4; r++) acc[i][j][r] = 0.f;

    auto load_tile = [&](int it, int stage) {
        __half* dA = hsmem + stage * STG_HALFS;
        __half* dB = dA + A_HALFS;
        const int kbase = it * 64;
        #pragma unroll
        for (int s = 0; s < 8; s++) {
            const int seg = s * 256 + tid;        // 0..2047
            const int r  = seg >> 3;              // 0..255
            const int kk = (seg & 7) << 3;        // 0..56
            cp_async16(dA + r * TSTRIDE + kk, A + (size_t)(m0 + r) * K + kbase + kk);
        }
        #pragma unroll
        for (int s = 0; s < 4; s++) {
            const int seg = s * 256 + tid;        // 0..1023
            const int r  = seg >> 3;              // 0..127
            const int kk = (seg & 7) << 3;
            cp_async16(dB + r * TSTRIDE + kk, B + (size_t)(n0 + r) * K + kbase + kk);
        }
        asm volatile("cp.async.commit_group;");
    };

    load_tile(0, 0);
    load_tile(1, 1);

    int st = 0, ldst = 2;
    for (int it = 0; it < NIT; it++) {
        asm volatile("cp.async.wait_group 1;");
        __syncthreads();

        if (it + 2 < NIT) {
            load_tile(it + 2, ldst);
            ldst = (ldst == 2) ? 0 : ldst + 1;
        }

        const __half* hA = hsmem + st * STG_HALFS;
        const __half* hB = hA + A_HALFS;
        st = (st == 2) ? 0 : st + 1;

        #pragma unroll
        for (int ks = 0; ks < 4; ks++) {
            uint32_t af[4][4], bf[4][4];
            #pragma unroll
            for (int i = 0; i < 4; i++)
                ldsm4(af[i], smem_u32(
                    &hA[(wm + 16 * i + (part & 1) * 8 + pr) * TSTRIDE + 16 * ks + (part >> 1) * 8]));
            #pragma unroll
            for (int j2 = 0; j2 < 4; j2++)
                ldsm4(bf[j2], smem_u32(
                    &hB[(wn + 8 * (2 * j2 + (part >> 1)) + pr) * TSTRIDE + 16 * ks + (part & 1) * 8]));
            #pragma unroll
            for (int i = 0; i < 4; i++)
                #pragma unroll
                for (int j = 0; j < 8; j++)
                    mma_f16(acc[i][j], af[i], bf[j >> 1] + (j & 1) * 2);
        }
    }

    // epilogue
    #pragma unroll
    for (int i = 0; i < 4; i++) {
        #pragma unroll
        for (int half = 0; half < 2; half++) {
            const int r = m0 + wm + i * 16 + gid + half * 8;
            const size_t rowoff = (size_t)r * N;
            #pragma unroll
            for (int j = 0; j < 8; j++) {
                const int c = n0 + wn + j * 8 + tig * 2;
                float v0 = acc[i][j][half * 2 + 0] + bias[c];
                float v1 = acc[i][j][half * 2 + 1] + bias[c + 1];
                if (EPI == 1) {
                    float2 r2 = *(const float2*)(Res + rowoff + c);
                    v0 += r2.x; v1 += r2.y;
                    float2 o; o.x = v0; o.y = v1;
                    *(float2*)((float*)Cout + rowoff + c) = o;
                } else {
                    if (EPI == 2) { v0 = fmaxf(v0, 0.f); v1 = fmaxf(v1, 0.f); }
                    *(__half2*)((__half*)Cout + rowoff + c) = __floats2half2_rn(v0, v1);
                }
            }
        }
    }
}

// ---------------------------------------------------------------------------
// Tensor-core causal flash attention, q-tile 128, kv-tile 64, 256 threads
// (8 warps x 16 q-rows). Double-buffered K/V; per-warp skip of fully-masked
// diagonal blocks; scale folded into exp via fmaf. Dynamic smem 55296 B.
// ---------------------------------------------------------------------------
#define ASTR 72
#define SQ_H (128 * ASTR)          // 9216 halfs
#define SKV_H (64 * ASTR)          // 4608 halfs per buffer
#define ATTN_SMEM ((SQ_H + 4 * SKV_H) * 2)   // 55296 B

__global__ __launch_bounds__(256)
void attn_kernel(const __half* __restrict__ qkv, __half* __restrict__ y) {
    extern __shared__ __half as[];
    __half* sQ = as;                    // [128][72]
    __half* sK = as + SQ_H;             // [2][64][72]
    __half* sV = as + SQ_H + 2 * SKV_H; // [2][64][72]

    const int tid  = threadIdx.x;
    const int warp = tid >> 5, lane = tid & 31;
    const int gid  = lane >> 2, tig = lane & 3;
    const int part = lane >> 3, pr = lane & 7;
    const int qb = blockIdx.x, h = blockIdx.y, b = blockIdx.z;
    const size_t base = (size_t)b * TT * (3 * CC) + (size_t)h * DD;

    // Q: 128 rows x 64 halfs
    #pragma unroll
    for (int i = 0; i < 4; i++) {
        const int seg = i * 256 + tid;        // 0..1023
        const int r = seg >> 3, c8 = (seg & 7) << 3;
        cp_async16(&sQ[r * ASTR + c8], qkv + base + (size_t)(qb * 128 + r) * (3 * CC) + c8);
    }
    // K/V block 0
    #pragma unroll
    for (int i = 0; i < 2; i++) {
        const int seg = i * 256 + tid;        // 0..511
        const int r = seg >> 3, c8 = (seg & 7) << 3;
        const size_t ka = base + CC + (size_t)r * (3 * CC) + c8;
        cp_async16(&sK[r * ASTR + c8], qkv + ka);
        cp_async16(&sV[r * ASTR + c8], qkv + ka + CC);
    }
    asm volatile("cp.async.commit_group;");

    float o[8][4];
    #pragma unroll
    for (int j = 0; j < 8; j++)
        #pragma unroll
        for (int r = 0; r < 4; r++) o[j][r] = 0.f;
    float m0 = -1e30f, m1 = -1e30f, l0 = 0.f, l1 = 0.f;
    uint32_t qf[4][4];

    const int arow0 = qb * 128 + 16 * warp + gid;   // absolute q row (first)
    const int wrow_max = qb * 128 + 16 * warp + 15;
    const int KBMAX = 2 * qb + 1;

    for (int kb = 0; kb <= KBMAX; kb++) {
        const int buf = kb & 1;
        if (kb < KBMAX) {
            #pragma unroll
            for (int i = 0; i < 2; i++) {
                const int seg = i * 256 + tid;
                const int r = seg >> 3, c8 = (seg & 7) << 3;
                const size_t ka = base + CC + (size_t)((kb + 1) * 64 + r) * (3 * CC) + c8;
                cp_async16(&sK[(buf ^ 1) * SKV_H + r * ASTR + c8], qkv + ka);
                cp_async16(&sV[(buf ^ 1) * SKV_H + r * ASTR + c8], qkv + ka + CC);
            }
            asm volatile("cp.async.commit_group;");
            asm volatile("cp.async.wait_group 1;");
        } else {
            asm volatile("cp.async.wait_group 0;");
        }
        __syncthreads();

        if (kb == 0) {
            #pragma unroll
            for (int ks = 0; ks < 4; ks++)
                ldsm4(qf[ks], smem_u32(
                    &sQ[(16 * warp + (part & 1) * 8 + pr) * ASTR + 16 * ks + (part >> 1) * 8]));
        }

        const bool skip = (64 * kb > wrow_max);   // block fully above diagonal
        if (!skip) {
            // --- S = Q K^T (raw, unscaled) ---
            float s[8][4];
            #pragma unroll
            for (int j = 0; j < 8; j++)
                #pragma unroll
                for (int r = 0; r < 4; r++) s[j][r] = 0.f;

            #pragma unroll
            for (int ks = 0; ks < 4; ks++) {
                #pragma unroll
                for (int j2 = 0; j2 < 8; j2 += 2) {
                    uint32_t kf[4];
                    ldsm4(kf, smem_u32(
                        &sK[buf * SKV_H + (8 * (j2 + (part >> 1)) + pr) * ASTR + 16 * ks + (part & 1) * 8]));
                    mma_f16(s[j2],     qf[ks], kf);
                    mma_f16(s[j2 + 1], qf[ks], kf + 2);
                }
            }

            // causal mask (absolute indices), only possible on last two blocks
            if (kb >= 2 * qb) {
                #pragma unroll
                for (int j = 0; j < 8; j++) {
                    const int c0 = 64 * kb + 8 * j + 2 * tig;
                    if (c0     > arow0)     s[j][0] = -1e30f;
                    if (c0 + 1 > arow0)     s[j][1] = -1e30f;
                    if (c0     > arow0 + 8) s[j][2] = -1e30f;
                    if (c0 + 1 > arow0 + 8) s[j][3] = -1e30f;
                }
            }

            // --- online softmax (scale folded into exp) ---
            float mx0 = -1e30f, mx1 = -1e30f;
            #pragma unroll
            for (int j = 0; j < 8; j++) {
                mx0 = fmaxf(mx0, fmaxf(s[j][0], s[j][1]));
                mx1 = fmaxf(mx1, fmaxf(s[j][2], s[j][3]));
            }
            mx0 = fmaxf(mx0, __shfl_xor_sync(0xffffffffu, mx0, 1));
            mx0 = fmaxf(mx0, __shfl_xor_sync(0xffffffffu, mx0, 2));
            mx1 = fmaxf(mx1, __shfl_xor_sync(0xffffffffu, mx1, 1));
            mx1 = fmaxf(mx1, __shfl_xor_sync(0xffffffffu, mx1, 2));

            const float mn0 = fmaxf(m0, mx0 * SCALE_ATTN);
            const float mn1 = fmaxf(m1, mx1 * SCALE_ATTN);
            const float cr0 = __expf(m0 - mn0), cr1 = __expf(m1 - mn1);
            m0 = mn0; m1 = mn1;

            float rs0 = 0.f, rs1 = 0.f;
            #pragma unroll
            for (int j = 0; j < 8; j++) {
                s[j][0] = __expf(fmaf(s[j][0], SCALE_ATTN, -mn0));
                s[j][1] = __expf(fmaf(s[j][1], SCALE_ATTN, -mn0));
                rs0 += s[j][0] + s[j][1];
                s[j][2] = __expf(fmaf(s[j][2], SCALE_ATTN, -mn1));
                s[j][3] = __expf(fmaf(s[j][3], SCALE_ATTN, -mn1));
                rs1 += s[j][2] + s[j][3];
            }
            rs0 += __shfl_xor_sync(0xffffffffu, rs0, 1);
            rs0 += __shfl_xor_sync(0xffffffffu, rs0, 2);
            rs1 += __shfl_xor_sync(0xffffffffu, rs1, 1);
            rs1 += __shfl_xor_sync(0xffffffffu, rs1, 2);
            l0 = l0 * cr0 + rs0;
            l1 = l1 * cr1 + rs1;
            #pragma unroll
            for (int j = 0; j < 8; j++) {
                o[j][0] *= cr0; o[j][1] *= cr0;
                o[j][2] *= cr1; o[j][3] *= cr1;
            }

            // --- O += P V ---
            #pragma unroll
            for (int kk = 0; kk < 4; kk++) {
                uint32_t pa[4];
                pa[0] = h2bits(s[2 * kk][0],     s[2 * kk][1]);
                pa[1] = h2bits(s[2 * kk][2],     s[2 * kk][3]);
                pa[2] = h2bits(s[2 * kk + 1][0], s[2 * kk + 1][1]);
                pa[3] = h2bits(s[2 * kk + 1][2], s[2 * kk + 1][3]);
                #pragma unroll
                for (int jd = 0; jd < 8; jd += 2) {
                    uint32_t vf[4];
                    ldsm4t(vf, smem_u32(
                        &sV[buf * SKV_H + (16 * kk + (part & 1) * 8 + pr) * ASTR + 8 * (jd + (part >> 1))]));
                    mma_f16(o[jd],     pa, vf);
                    mma_f16(o[jd + 1], pa, vf + 2);
                }
            }
        }
        __syncthreads();
    }

    const float i0 = 1.f / l0, i1 = 1.f / l1;
    const int r0 = qb * 128 + 16 * warp + gid;
    #pragma unroll
    for (int j = 0; j < 8; j++) {
        const int col = h * DD + 8 * j + 2 * tig;
        *(__half2*)(y + (size_t)(b * TT + r0) * CC + col) =
            __floats2half2_rn(o[j][0] * i0, o[j][1] * i0);
        *(__half2*)(y + (size_t)(b * TT + r0 + 8) * CC + col) =
            __floats2half2_rn(o[j][2] * i1, o[j][3] * i1);
    }
}

// ---------------------------------------------------------------------------
// Launch
// ---------------------------------------------------------------------------
extern "C" void kernel_launch(void* const* d_in, const int* in_sizes, int n_in,
                              void* d_out, int out_size) {
    const float* x     = (const float*)d_in[0];
    const float* Wqkv  = (const float*)d_in[1];
    const float* bqkv  = (const float*)d_in[2];
    const float* Wproj = (const float*)d_in[3];
    const float* bproj = (const float*)d_in[4];
    const float* ln1_g = (const float*)d_in[5];
    const float* ln1_b = (const float*)d_in[6];
    const float* ln2_g = (const float*)d_in[7];
    const float* ln2_b = (const float*)d_in[8];
    const float* W1    = (const float*)d_in[9];
    const float* b1    = (const float*)d_in[10];
    const float* W2    = (const float*)d_in[11];
    const float* b2    = (const float*)d_in[12];
    float* out = (float*)d_out;

    __half *h, *qkv, *y, *h2, *mid, *wt;
    cudaGetSymbolAddress((void**)&h,   g_h);
    cudaGetSymbolAddress((void**)&qkv, g_qkv);
    cudaGetSymbolAddress((void**)&y,   g_y);
    cudaGetSymbolAddress((void**)&h2,  g_h2);
    cudaGetSymbolAddress((void**)&mid, g_mid);
    cudaGetSymbolAddress((void**)&wt,  g_wt);

    static int smem_set = 0;
    if (!smem_set) {
        cudaFuncSetAttribute(hgemm_kernel<0>, cudaFuncAttributeMaxDynamicSharedMemorySize, GEMM_SMEM);
        cudaFuncSetAttribute(hgemm_kernel<1>, cudaFuncAttributeMaxDynamicSharedMemorySize, GEMM_SMEM);
        cudaFuncSetAttribute(hgemm_kernel<2>, cudaFuncAttributeMaxDynamicSharedMemorySize, GEMM_SMEM);
        cudaFuncSetAttribute(attn_kernel, cudaFuncAttributeMaxDynamicSharedMemorySize, ATTN_SMEM);
        smem_set = 1;
    }

    // 0. transpose + fp16-round weights: Wt[N][K]
    transpose_w<<<dim3(3 * CC / 32, CC / 32), dim3(32, 8)>>>(Wqkv,  wt + OFF_QKV,  CC, 3 * CC);
    transpose_w<<<dim3(CC / 32, CC / 32),     dim3(32, 8)>>>(Wproj, wt + OFF_PROJ, CC, CC);
    transpose_w<<<dim3(4 * CC / 32, CC / 32), dim3(32, 8)>>>(W1,    wt + OFF_W1,   CC, 4 * CC);
    transpose_w<<<dim3(CC / 32, 4 * CC / 32), dim3(32, 8)>>>(W2,    wt + OFF_W2,   4 * CC, CC);

    // 1. h = ln1(x)
    ln_kernel<<<NTOK, 256>>>(x, ln1_g, ln1_b, h);
    // 2. qkv = h @ Wqkv + bqkv   (half out)
    hgemm_kernel<0><<<dim3(3 * CC / 128, NTOK / 256), 256, GEMM_SMEM>>>(
        h, wt + OFF_QKV, bqkv, nullptr, qkv, NTOK, 3 * CC, CC);
    // 3. y = causal_attention(qkv)   (tensor-core FA, q-tile 128)
    attn_kernel<<<dim3(TT / 128, HH, BB), 256, ATTN_SMEM>>>(qkv, y);
    // 4. out = x + y @ Wproj + bproj   (float out)
    hgemm_kernel<1><<<dim3(CC / 128, NTOK / 256), 256, GEMM_SMEM>>>(
        y, wt + OFF_PROJ, bproj, x, out, NTOK, CC, CC);
    // 5. h2 = ln2(out)
    ln_kernel<<<NTOK, 256>>>(out, ln2_g, ln2_b, h2);
    // 6. mid = relu(h2 @ W1 + b1)   (half out)
    hgemm_kernel<2><<<dim3(4 * CC / 128, NTOK / 256), 256, GEMM_SMEM>>>(
        h2, wt + OFF_W1, b1, nullptr, mid, NTOK, 4 * CC, CC);
    // 7. out = out + mid @ W2 + b2   (float out, K=4096)
    hgemm_kernel<1><<<dim3(CC / 128, NTOK / 256), 256, GEMM_SMEM>>>(
        mid, wt + OFF_W2, b2, out, out, NTOK, CC, 4 * CC);
}

// round 12
// speedup vs baseline: 3.3227x; 1.0171x over previous
#include <cuda_runtime.h>
#include <cuda_fp16.h>
#include <cstdint>

// ---------------------------------------------------------------------------
// Problem constants
// ---------------------------------------------------------------------------
#define BB 8
#define TT 1024
#define CC 1024
#define HH 16
#define DD 64
#define NTOK (BB * TT)           // 8192
#define SCALE_ATTN 0.07216878364870323f  // 1/sqrt(3*C/H) = 1/sqrt(192)

// ---------------------------------------------------------------------------
// Scratch (device globals) — fp16 activations
// ---------------------------------------------------------------------------
__device__ __half g_h[NTOK * CC];          // ln1 out
__device__ __half g_qkv[NTOK * 3 * CC];    // qkv
__device__ __half g_y[NTOK * CC];          // attn out
__device__ __half g_h2[NTOK * CC];         // ln2 out
__device__ __half g_mid[NTOK * 4 * CC];    // mlp hidden
// transposed fp16 weights, [N][K] row-major
#define OFF_QKV  0
#define OFF_PROJ (3 * CC * CC)
#define OFF_W1   (OFF_PROJ + CC * CC)
#define OFF_W2   (OFF_W1 + 4 * CC * CC)
#define WP_TOTAL (OFF_W2 + 4 * CC * CC)
__device__ __half g_wt[WP_TOTAL];

// ---------------------------------------------------------------------------
// Helpers
// ---------------------------------------------------------------------------
__device__ __forceinline__ void mma_f16(float* c, const uint32_t* a, const uint32_t* b) {
    asm volatile(
        "mma.sync.aligned.m16n8k16.row.col.f32.f16.f16.f32 "
        "{%0,%1,%2,%3}, {%4,%5,%6,%7}, {%8,%9}, {%0,%1,%2,%3};"
        : "+f"(c[0]), "+f"(c[1]), "+f"(c[2]), "+f"(c[3])
        : "r"(a[0]), "r"(a[1]), "r"(a[2]), "r"(a[3]), "r"(b[0]), "r"(b[1]));
}

__device__ __forceinline__ void cp_async16(void* smem_ptr, const void* gptr) {
    uint32_t sp = (uint32_t)__cvta_generic_to_shared(smem_ptr);
    asm volatile("cp.async.ca.shared.global [%0], [%1], 16;" :: "r"(sp), "l"(gptr));
}

__device__ __forceinline__ uint32_t smem_u32(const void* p) {
    return (uint32_t)__cvta_generic_to_shared(p);
}

__device__ __forceinline__ void ldsm4(uint32_t* r, uint32_t a) {
    asm volatile("ldmatrix.sync.aligned.m8n8.x4.shared.b16 {%0,%1,%2,%3}, [%4];"
        : "=r"(r[0]), "=r"(r[1]), "=r"(r[2]), "=r"(r[3]) : "r"(a));
}
__device__ __forceinline__ void ldsm4t(uint32_t* r, uint32_t a) {
    asm volatile("ldmatrix.sync.aligned.m8n8.x4.trans.shared.b16 {%0,%1,%2,%3}, [%4];"
        : "=r"(r[0]), "=r"(r[1]), "=r"(r[2]), "=r"(r[3]) : "r"(a));
}

__device__ __forceinline__ uint32_t h2bits(float a, float b) {
    __half2 h = __floats2half2_rn(a, b);
    return *reinterpret_cast<uint32_t*>(&h);
}

// ---------------------------------------------------------------------------
// Weight transpose + fp16 round: W[K][N] fp32 -> Wt[N][K] fp16
// ---------------------------------------------------------------------------
__global__ __launch_bounds__(256)
void transpose_w(const float* __restrict__ W, __half* __restrict__ Wt, int K, int N) {
    __shared__ float t[32][33];
    const int n0 = blockIdx.x * 32;
    const int k0 = blockIdx.y * 32;
    const int tx = threadIdx.x, ty = threadIdx.y;
    #pragma unroll
    for (int i = 0; i < 4; i++)
        t[ty + 8 * i][tx] = W[(size_t)(k0 + ty + 8 * i) * N + n0 + tx];
    __syncthreads();
    #pragma unroll
    for (int i = 0; i < 4; i++)
        Wt[(size_t)(n0 + ty + 8 * i) * K + k0 + tx] = __float2half_rn(t[tx][ty + 8 * i]);
}

// ---------------------------------------------------------------------------
// LayerNorm: one block per row; fp32 in -> fp16 out
// ---------------------------------------------------------------------------
__global__ __launch_bounds__(256)
void ln_kernel(const float* __restrict__ x, const float* __restrict__ g,
               const float* __restrict__ b, __half* __restrict__ out) {
    __shared__ float rs[8];
    __shared__ float rq[8];
    const int row = blockIdx.x;
    const float* xr = x + (size_t)row * CC;
    __half* yr = out + (size_t)row * CC;
    const int c = threadIdx.x * 4;

    float4 v = *(const float4*)(xr + c);
    float s  = v.x + v.y + v.z + v.w;
    float sq = v.x * v.x + v.y * v.y + v.z * v.z + v.w * v.w;
    #pragma unroll
    for (int o = 16; o; o >>= 1) {
        s  += __shfl_xor_sync(0xffffffffu, s, o);
        sq += __shfl_xor_sync(0xffffffffu, sq, o);
    }
    if ((threadIdx.x & 31) == 0) { rs[threadIdx.x >> 5] = s; rq[threadIdx.x >> 5] = sq; }
    __syncthreads();
    s = 0.f; sq = 0.f;
    #pragma unroll
    for (int i = 0; i < 8; i++) { s += rs[i]; sq += rq[i]; }

    const float mean = s * (1.f / CC);
    const float var  = sq * (1.f / CC) - mean * mean;
    const float rstd = rsqrtf(var + 1e-5f);

    float4 g4 = *(const float4*)(g + c);
    float4 b4 = *(const float4*)(b + c);
    *(__half2*)(yr + c)     = __floats2half2_rn((v.x - mean) * rstd * g4.x + b4.x,
                                                (v.y - mean) * rstd * g4.y + b4.y);
    *(__half2*)(yr + c + 2) = __floats2half2_rn((v.z - mean) * rstd * g4.z + b4.z,
                                                (v.w - mean) * rstd * g4.w + b4.w);
}

// ---------------------------------------------------------------------------
// FP16 tensor GEMM: C[M,N] = A[M,K] @ Wt[N,K]^T + bias (+Res | relu)
// CTA tile 256x128, BK=64, 3-stage cp.async, one sync per k-iter,
// 8 warps (4m x 2n), warp tile 64x64, register double-buffered ldmatrix feed.
// EPI: 0 = bias -> half, 1 = bias + residual -> float, 2 = bias + relu -> half
// ---------------------------------------------------------------------------
#define STAGES 3
#define TSTRIDE 72                       // halfs per row (BK=64 + pad 8)
#define A_HALFS (256 * TSTRIDE)          // 18432 halfs
#define B_HALFS (128 * TSTRIDE)          // 9216 halfs
#define STG_HALFS (A_HALFS + B_HALFS)    // 27648 halfs
#define GEMM_SMEM (STAGES * STG_HALFS * 2)   // 165888 B

template <int EPI>
__global__ __launch_bounds__(256, 1)
void hgemm_kernel(const __half* __restrict__ A, const __half* __restrict__ B,
                  const float* __restrict__ bias, const float* __restrict__ Res,
                  void* __restrict__ Cout, int M, int N, int K) {
    extern __shared__ __half hsmem[];

    const int tid  = threadIdx.x;
    const int warp = tid >> 5;
    const int lane = tid & 31;
    const int gid  = lane >> 2;
    const int tig  = lane & 3;
    const int part = lane >> 3, pr = lane & 7;
    const int wm   = (warp >> 1) * 64;   // m offset (4 warp-rows)
    const int wn   = (warp & 1) * 64;    // n offset (2 warp-cols)
    const int m0   = blockIdx.y * 256;
    const int n0   = blockIdx.x * 128;
    const int NIT  = K >> 6;

    float acc[4][8][4];
    #pragma unroll
    for (int i = 0; i < 4; i++)
        #pragma unroll
        for (int j = 0; j < 8; j++)
            #pragma unroll
            for (int r = 0; r < 4; r++) acc[i][j][r] = 0.f;

    auto load_tile = [&](int it, int stage) {
        __half* dA = hsmem + stage * STG_HALFS;
        __half* dB = dA + A_HALFS;
        const int kbase = it * 64;
        #pragma unroll
        for (int s = 0; s < 8; s++) {
            const int seg = s * 256 + tid;        // 0..2047
            const int r  = seg >> 3;              // 0..255
            const int kk = (seg & 7) << 3;        // 0..56
            cp_async16(dA + r * TSTRIDE + kk, A + (size_t)(m0 + r) * K + kbase + kk);
        }
        #pragma unroll
        for (int s = 0; s < 4; s++) {
            const int seg = s * 256 + tid;        // 0..1023
            const int r  = seg >> 3;              // 0..127
            const int kk = (seg & 7) << 3;
            cp_async16(dB + r * TSTRIDE + kk, B + (size_t)(n0 + r) * K + kbase + kk);
        }
        asm volatile("cp.async.commit_group;");
    };

    load_tile(0, 0);
    load_tile(1, 1);

    // per-warp base rows (constant across iters)
    const int arow = (part & 1) * 8 + pr;         // within warp A 16-row group
    const int brow = (part >> 1) * 8 + pr;        // wait: B uses different mapping
    (void)brow;

    int st = 0, ldst = 2;
    for (int it = 0; it < NIT; it++) {
        asm volatile("cp.async.wait_group 1;");
        __syncthreads();

        if (it + 2 < NIT) {
            load_tile(it + 2, ldst);
            ldst = (ldst == 2) ? 0 : ldst + 1;
        }

        const __half* hA = hsmem + st * STG_HALFS;
        const __half* hB = hA + A_HALFS;
        st = (st == 2) ? 0 : st + 1;

        uint32_t af[2][4][4], bf[2][4][4];

        auto ld_frags = [&](int ks, uint32_t a_[4][4], uint32_t b_[4][4]) {
            #pragma unroll
            for (int i = 0; i < 4; i++)
                ldsm4(a_[i], smem_u32(
                    &hA[(wm + 16 * i + arow) * TSTRIDE + 16 * ks + (part >> 1) * 8]));
            #pragma unroll
            for (int j2 = 0; j2 < 4; j2++)
                ldsm4(b_[j2], smem_u32(
                    &hB[(wn + 8 * (2 * j2 + (part >> 1)) + pr) * TSTRIDE + 16 * ks + (part & 1) * 8]));
        };

        ld_frags(0, af[0], bf[0]);
        #pragma unroll
        for (int ks = 0; ks < 4; ks++) {
            const int cur = ks & 1;
            if (ks < 3) ld_frags(ks + 1, af[cur ^ 1], bf[cur ^ 1]);
            #pragma unroll
            for (int i = 0; i < 4; i++)
                #pragma unroll
                for (int j = 0; j < 8; j++)
                    mma_f16(acc[i][j], af[cur][i], bf[cur][j >> 1] + (j & 1) * 2);
        }
    }

    // epilogue
    #pragma unroll
    for (int i = 0; i < 4; i++) {
        #pragma unroll
        for (int half = 0; half < 2; half++) {
            const int r = m0 + wm + i * 16 + gid + half * 8;
            const size_t rowoff = (size_t)r * N;
            #pragma unroll
            for (int j = 0; j < 8; j++) {
                const int c = n0 + wn + j * 8 + tig * 2;
                float v0 = acc[i][j][half * 2 + 0] + bias[c];
                float v1 = acc[i][j][half * 2 + 1] + bias[c + 1];
                if (EPI == 1) {
                    float2 r2 = *(const float2*)(Res + rowoff + c);
                    v0 += r2.x; v1 += r2.y;
                    float2 o; o.x = v0; o.y = v1;
                    *(float2*)((float*)Cout + rowoff + c) = o;
                } else {
                    if (EPI == 2) { v0 = fmaxf(v0, 0.f); v1 = fmaxf(v1, 0.f); }
                    *(__half2*)((__half*)Cout + rowoff + c) = __floats2half2_rn(v0, v1);
                }
            }
        }
    }
}

// ---------------------------------------------------------------------------
// Tensor-core causal flash attention, q-tile 128, kv-tile 64, 256 threads.
// ---------------------------------------------------------------------------
#define ASTR 72
#define SQ_H (128 * ASTR)          // 9216 halfs
#define SKV_H (64 * ASTR)          // 4608 halfs per buffer
#define ATTN_SMEM ((SQ_H + 4 * SKV_H) * 2)   // 55296 B

__global__ __launch_bounds__(256)
void attn_kernel(const __half* __restrict__ qkv, __half* __restrict__ y) {
    extern __shared__ __half as[];
    __half* sQ = as;                    // [128][72]
    __half* sK = as + SQ_H;             // [2][64][72]
    __half* sV = as + SQ_H + 2 * SKV_H; // [2][64][72]

    const int tid  = threadIdx.x;
    const int warp = tid >> 5, lane = tid & 31;
    const int gid  = lane >> 2, tig = lane & 3;
    const int part = lane >> 3, pr = lane & 7;
    const int qb = blockIdx.x, h = blockIdx.y, b = blockIdx.z;
    const size_t base = (size_t)b * TT * (3 * CC) + (size_t)h * DD;

    #pragma unroll
    for (int i = 0; i < 4; i++) {
        const int seg = i * 256 + tid;
        const int r = seg >> 3, c8 = (seg & 7) << 3;
        cp_async16(&sQ[r * ASTR + c8], qkv + base + (size_t)(qb * 128 + r) * (3 * CC) + c8);
    }
    #pragma unroll
    for (int i = 0; i < 2; i++) {
        const int seg = i * 256 + tid;
        const int r = seg >> 3, c8 = (seg & 7) << 3;
        const size_t ka = base + CC + (size_t)r * (3 * CC) + c8;
        cp_async16(&sK[r * ASTR + c8], qkv + ka);
        cp_async16(&sV[r * ASTR + c8], qkv + ka + CC);
    }
    asm volatile("cp.async.commit_group;");

    float o[8][4];
    #pragma unroll
    for (int j = 0; j < 8; j++)
        #pragma unroll
        for (int r = 0; r < 4; r++) o[j][r] = 0.f;
    float m0 = -1e30f, m1 = -1e30f, l0 = 0.f, l1 = 0.f;
    uint32_t qf[4][4];

    const int arow0 = qb * 128 + 16 * warp + gid;
    const int wrow_max = qb * 128 + 16 * warp + 15;
    const int KBMAX = 2 * qb + 1;

    for (int kb = 0; kb <= KBMAX; kb++) {
        const int buf = kb & 1;
        if (kb < KBMAX) {
            #pragma unroll
            for (int i = 0; i < 2; i++) {
                const int seg = i * 256 + tid;
                const int r = seg >> 3, c8 = (seg & 7) << 3;
                const size_t ka = base + CC + (size_t)((kb + 1) * 64 + r) * (3 * CC) + c8;
                cp_async16(&sK[(buf ^ 1) * SKV_H + r * ASTR + c8], qkv + ka);
                cp_async16(&sV[(buf ^ 1) * SKV_H + r * ASTR + c8], qkv + ka + CC);
            }
            asm volatile("cp.async.commit_group;");
            asm volatile("cp.async.wait_group 1;");
        } else {
            asm volatile("cp.async.wait_group 0;");
        }
        __syncthreads();

        if (kb == 0) {
            #pragma unroll
            for (int ks = 0; ks < 4; ks++)
                ldsm4(qf[ks], smem_u32(
                    &sQ[(16 * warp + (part & 1) * 8 + pr) * ASTR + 16 * ks + (part >> 1) * 8]));
        }

        const bool skip = (64 * kb > wrow_max);
        if (!skip) {
            float s[8][4];
            #pragma unroll
            for (int j = 0; j < 8; j++)
                #pragma unroll
                for (int r = 0; r < 4; r++) s[j][r] = 0.f;

            #pragma unroll
            for (int ks = 0; ks < 4; ks++) {
                #pragma unroll
                for (int j2 = 0; j2 < 8; j2 += 2) {
                    uint32_t kf[4];
                    ldsm4(kf, smem_u32(
                        &sK[buf * SKV_H + (8 * (j2 + (part >> 1)) + pr) * ASTR + 16 * ks + (part & 1) * 8]));
                    mma_f16(s[j2],     qf[ks], kf);
                    mma_f16(s[j2 + 1], qf[ks], kf + 2);
                }
            }

            if (kb >= 2 * qb) {
                #pragma unroll
                for (int j = 0; j < 8; j++) {
                    const int c0 = 64 * kb + 8 * j + 2 * tig;
                    if (c0     > arow0)     s[j][0] = -1e30f;
                    if (c0 + 1 > arow0)     s[j][1] = -1e30f;
                    if (c0     > arow0 + 8) s[j][2] = -1e30f;
                    if (c0 + 1 > arow0 + 8) s[j][3] = -1e30f;
                }
            }

            float mx0 = -1e30f, mx1 = -1e30f;
            #pragma unroll
            for (int j = 0; j < 8; j++) {
                mx0 = fmaxf(mx0, fmaxf(s[j][0], s[j][1]));
                mx1 = fmaxf(mx1, fmaxf(s[j][2], s[j][3]));
            }
            mx0 = fmaxf(mx0, __shfl_xor_sync(0xffffffffu, mx0, 1));
            mx0 = fmaxf(mx0, __shfl_xor_sync(0xffffffffu, mx0, 2));
            mx1 = fmaxf(mx1, __shfl_xor_sync(0xffffffffu, mx1, 1));
            mx1 = fmaxf(mx1, __shfl_xor_sync(0xffffffffu, mx1, 2));

            const float mn0 = fmaxf(m0, mx0 * SCALE_ATTN);
            const float mn1 = fmaxf(m1, mx1 * SCALE_ATTN);
            const float cr0 = __expf(m0 - mn0), cr1 = __expf(m1 - mn1);
            m0 = mn0; m1 = mn1;

            float rs0 = 0.f, rs1 = 0.f;
            #pragma unroll
            for (int j = 0; j < 8; j++) {
                s[j][0] = __expf(fmaf(s[j][0], SCALE_ATTN, -mn0));
                s[j][1] = __expf(fmaf(s[j][1], SCALE_ATTN, -mn0));
                rs0 += s[j][0] + s[j][1];
                s[j][2] = __expf(fmaf(s[j][2], SCALE_ATTN, -mn1));
                s[j][3] = __expf(fmaf(s[j][3], SCALE_ATTN, -mn1));
                rs1 += s[j][2] + s[j][3];
            }
            rs0 += __shfl_xor_sync(0xffffffffu, rs0, 1);
            rs0 += __shfl_xor_sync(0xffffffffu, rs0, 2);
            rs1 += __shfl_xor_sync(0xffffffffu, rs1, 1);
            rs1 += __shfl_xor_sync(0xffffffffu, rs1, 2);
            l0 = l0 * cr0 + rs0;
            l1 = l1 * cr1 + rs1;
            #pragma unroll
            for (int j = 0; j < 8; j++) {
                o[j][0] *= cr0; o[j][1] *= cr0;
                o[j][2] *= cr1; o[j][3] *= cr1;
            }

            #pragma unroll
            for (int kk = 0; kk < 4; kk++) {
                uint32_t pa[4];
                pa[0] = h2bits(s[2 * kk][0],     s[2 * kk][1]);
                pa[1] = h2bits(s[2 * kk][2],     s[2 * kk][3]);
                pa[2] = h2bits(s[2 * kk + 1][0], s[2 * kk + 1][1]);
                pa[3] = h2bits(s[2 * kk + 1][2], s[2 * kk + 1][3]);
                #pragma unroll
                for (int jd = 0; jd < 8; jd += 2) {
                    uint32_t vf[4];
                    ldsm4t(vf, smem_u32(
                        &sV[buf * SKV_H + (16 * kk + (part & 1) * 8 + pr) * ASTR + 8 * (jd + (part >> 1))]));
                    mma_f16(o[jd],     pa, vf);
                    mma_f16(o[jd + 1], pa, vf + 2);
                }
            }
        }
        __syncthreads();
    }

    const float i0 = 1.f / l0, i1 = 1.f / l1;
    const int r0 = qb * 128 + 16 * warp + gid;
    #pragma unroll
    for (int j = 0; j < 8; j++) {
        const int col = h * DD + 8 * j + 2 * tig;
        *(__half2*)(y + (size_t)(b * TT + r0) * CC + col) =
            __floats2half2_rn(o[j][0] * i0, o[j][1] * i0);
        *(__half2*)(y + (size_t)(b * TT + r0 + 8) * CC + col) =
            __floats2half2_rn(o[j][2] * i1, o[j][3] * i1);
    }
}

// ---------------------------------------------------------------------------
// Launch — transposes overlapped on a side stream (fork-join, graph-capturable)
// ---------------------------------------------------------------------------
extern "C" void kernel_launch(void* const* d_in, const int* in_sizes, int n_in,
                              void* d_out, int out_size) {
    const float* x     = (const float*)d_in[0];
    const float* Wqkv  = (const float*)d_in[1];
    const float* bqkv  = (const float*)d_in[2];
    const float* Wproj = (const float*)d_in[3];
    const float* bproj = (const float*)d_in[4];
    const float* ln1_g = (const float*)d_in[5];
    const float* ln1_b = (const float*)d_in[6];
    const float* ln2_g = (const float*)d_in[7];
    const float* ln2_b = (const float*)d_in[8];
    const float* W1    = (const float*)d_in[9];
    const float* b1    = (const float*)d_in[10];
    const float* W2    = (const float*)d_in[11];
    const float* b2    = (const float*)d_in[12];
    float* out = (float*)d_out;

    __half *h, *qkv, *y, *h2, *mid, *wt;
    cudaGetSymbolAddress((void**)&h,   g_h);
    cudaGetSymbolAddress((void**)&qkv, g_qkv);
    cudaGetSymbolAddress((void**)&y,   g_y);
    cudaGetSymbolAddress((void**)&h2,  g_h2);
    cudaGetSymbolAddress((void**)&mid, g_mid);
    cudaGetSymbolAddress((void**)&wt,  g_wt);

    static cudaStream_t s_side = nullptr;
    static cudaEvent_t ev_fork = nullptr, ev_qkv = nullptr, ev_rest = nullptr;
    static int init_done = 0;
    if (!init_done) {
        cudaFuncSetAttribute(hgemm_kernel<0>, cudaFuncAttributeMaxDynamicSharedMemorySize, GEMM_SMEM);
        cudaFuncSetAttribute(hgemm_kernel<1>, cudaFuncAttributeMaxDynamicSharedMemorySize, GEMM_SMEM);
        cudaFuncSetAttribute(hgemm_kernel<2>, cudaFuncAttributeMaxDynamicSharedMemorySize, GEMM_SMEM);
        cudaFuncSetAttribute(attn_kernel, cudaFuncAttributeMaxDynamicSharedMemorySize, ATTN_SMEM);
        cudaStreamCreateWithFlags(&s_side, cudaStreamNonBlocking);
        cudaEventCreateWithFlags(&ev_fork, cudaEventDisableTiming);
        cudaEventCreateWithFlags(&ev_qkv,  cudaEventDisableTiming);
        cudaEventCreateWithFlags(&ev_rest, cudaEventDisableTiming);
        init_done = 1;
    }

    // fork: side stream does the 4 weight transposes
    cudaEventRecord(ev_fork, 0);
    cudaStreamWaitEvent(s_side, ev_fork, 0);
    transpose_w<<<dim3(3 * CC / 32, CC / 32), dim3(32, 8), 0, s_side>>>(Wqkv, wt + OFF_QKV, CC, 3 * CC);
    cudaEventRecord(ev_qkv, s_side);
    transpose_w<<<dim3(CC / 32, CC / 32),     dim3(32, 8), 0, s_side>>>(Wproj, wt + OFF_PROJ, CC, CC);
    transpose_w<<<dim3(4 * CC / 32, CC / 32), dim3(32, 8), 0, s_side>>>(W1,    wt + OFF_W1,   CC, 4 * CC);
    transpose_w<<<dim3(CC / 32, 4 * CC / 32), dim3(32, 8), 0, s_side>>>(W2,    wt + OFF_W2,   4 * CC, CC);
    cudaEventRecord(ev_rest, s_side);

    // main stream: ln1 overlaps with transposes
    ln_kernel<<<NTOK, 256>>>(x, ln1_g, ln1_b, h);
    cudaStreamWaitEvent(0, ev_qkv, 0);
    // 2. qkv = h @ Wqkv + bqkv   (half out)
    hgemm_kernel<0><<<dim3(3 * CC / 128, NTOK / 256), 256, GEMM_SMEM>>>(
        h, wt + OFF_QKV, bqkv, nullptr, qkv, NTOK, 3 * CC, CC);
    // 3. y = causal_attention(qkv)
    attn_kernel<<<dim3(TT / 128, HH, BB), 256, ATTN_SMEM>>>(qkv, y);
    cudaStreamWaitEvent(0, ev_rest, 0);
    // 4. out = x + y @ Wproj + bproj   (float out)
    hgemm_kernel<1><<<dim3(CC / 128, NTOK / 256), 256, GEMM_SMEM>>>(
        y, wt + OFF_PROJ, bproj, x, out, NTOK, CC, CC);
    // 5. h2 = ln2(out)
    ln_kernel<<<NTOK, 256>>>(out, ln2_g, ln2_b, h2);
    // 6. mid = relu(h2 @ W1 + b1)   (half out)
    hgemm_kernel<2><<<dim3(4 * CC / 128, NTOK / 256), 256, GEMM_SMEM>>>(
        h2, wt + OFF_W1, b1, nullptr, mid, NTOK, 4 * CC, CC);
    // 7. out = out + mid @ W2 + b2   (float out, K=4096)
    hgemm_kernel<1><<<dim3(CC / 128, NTOK / 256), 256, GEMM_SMEM>>>(
        mid, wt + OFF_W2, b2, out, out, NTOK, CC, 4 * CC);
}